// round 8
// baseline (speedup 1.0000x reference)
#include <cuda_runtime.h>
#include <cuda_bf16.h>

#define N_NODES  100000
#define N_EDGES  1600000
#define N_GRAPHS 1000
#define SCAN_B   1024
#define N_SBLK   ((N_NODES + SCAN_B - 1) / SCAN_B)   // 98

// ---------------- scratch (static __device__, no allocs) ----------------
__device__ float g_deg[N_NODES];
__device__ float g_dinv[N_NODES];
__device__ int   g_cnt[N_NODES];
__device__ int   g_rank[N_EDGES];
__device__ int   g_rs[N_NODES + 1];
__device__ int   g_bsum[N_SBLK];
__device__ int2  g_csr[N_EDGES];          // {src, weight-as-bits}
__device__ float g_m[N_NODES * 64];
__device__ float g_m2[N_NODES * 32];
__device__ float g_h2[N_NODES * 32];

// ---------------- degree + in-degree count + rank capture ----------------
__global__ void edge_prep_kernel(const int* __restrict__ dst, const float* __restrict__ w, int E) {
    int e = blockIdx.x * blockDim.x + threadIdx.x;
    if (e < E) {
        int d = dst[e];
        atomicAdd(&g_deg[d], w[e]);
        g_rank[e] = atomicAdd(&g_cnt[d], 1);   // coalesced rank store
    }
}

// ---------------- fused dinv + scan stage 1 ----------------
__global__ void dinv_scan1_kernel(int n) {
    __shared__ int wsum[32];
    int i = blockIdx.x * SCAN_B + threadIdx.x;
    int lane = threadIdx.x & 31, wid = threadIdx.x >> 5;

    if (i < n) {
        float d = g_deg[i] + 1.0f;  // self loop weight 1
        g_dinv[i] = rsqrtf(fmaxf(d, 1e-12f));
    }
    if (i == 0) g_rs[0] = 0;

    int v = (i < n) ? g_cnt[i] : 0;
    int s = v;
#pragma unroll
    for (int o = 1; o < 32; o <<= 1) {
        int t = __shfl_up_sync(0xffffffffu, s, o);
        if (lane >= o) s += t;
    }
    if (lane == 31) wsum[wid] = s;
    __syncthreads();
    if (wid == 0) {
        int ws = wsum[lane];
#pragma unroll
        for (int o = 1; o < 32; o <<= 1) {
            int t = __shfl_up_sync(0xffffffffu, ws, o);
            if (lane >= o) ws += t;
        }
        wsum[lane] = ws;
    }
    __syncthreads();
    int off = (wid > 0) ? wsum[wid - 1] : 0;
    int incl = s + off;
    if (i < n) g_rs[i + 1] = incl;
    if (threadIdx.x == SCAN_B - 1) g_bsum[blockIdx.x] = incl;
}

// ---------------- scan stage 2+3 merged: each block computes its own prefix ----------------
__global__ void scan23_kernel(int n) {
    __shared__ int pref;
    if (blockIdx.x == 0) return;
    if (threadIdx.x == 0) {
        int s = 0;
        for (int j = 0; j < (int)blockIdx.x; j++) s += g_bsum[j];
        pref = s;
    }
    __syncthreads();
    int i = blockIdx.x * SCAN_B + threadIdx.x;
    if (i < n) g_rs[i + 1] += pref;
}

// ---------------- scatter into CSR (atomic-free, single packed STG.64) ----------------
__global__ void scatter_kernel(const int* __restrict__ src, const int* __restrict__ dst,
                               const float* __restrict__ w, int E) {
    int e = blockIdx.x * blockDim.x + threadIdx.x;
    if (e >= E) return;
    int s = src[e], d = dst[e];
    int pos = g_rs[d] + g_rank[e];
    float nw = g_dinv[s] * w[e] * g_dinv[d];
    g_csr[pos] = make_int2(s, __float_as_int(nw));
}

// ---------------- register-blocked GEMM: out[N,M] = X[N,K] @ W[K,M] ----------------
template <int K, int M, int TR, int KP>
__global__ void __launch_bounds__(TR * M / 32)
gemm_kernel(const float* __restrict__ X, const float* __restrict__ W,
            float* __restrict__ out, int nrows) {
    __shared__ float Ws[KP * M];
    __shared__ float Xs[TR * KP];
    constexpr int T = TR * M / 32;

    int row0 = blockIdx.x * TR;
    int nr = nrows - row0; if (nr > TR) nr = TR;
    const float4* Xg = reinterpret_cast<const float4*>(X);

    int tx = threadIdx.x % (M / 8);
    int ty = threadIdx.x / (M / 8);
    int c0 = tx * 8;
    int r0 = ty * 4;

    float acc[4][8];
#pragma unroll
    for (int r = 0; r < 4; r++)
#pragma unroll
        for (int c = 0; c < 8; c++) acc[r][c] = 0.f;

    for (int ph = 0; ph < K; ph += KP) {
        for (int i = threadIdx.x; i < KP * M / 4; i += T)
            reinterpret_cast<float4*>(Ws)[i] = reinterpret_cast<const float4*>(W + ph * M)[i];
        for (int i = threadIdx.x; i < nr * (KP / 4); i += T) {
            int row = i / (KP / 4), col = i % (KP / 4);
            reinterpret_cast<float4*>(Xs)[row * (KP / 4) + col] =
                Xg[((size_t)(row0 + row) * K + ph) / 4 + col];
        }
        __syncthreads();

#pragma unroll 2
        for (int kc = 0; kc < KP; kc += 4) {
            float4 xa[4];
#pragma unroll
            for (int r = 0; r < 4; r++)
                xa[r] = *reinterpret_cast<const float4*>(&Xs[(r0 + r) * KP + kc]);
#pragma unroll
            for (int kk = 0; kk < 4; kk++) {
                float4 wa = *reinterpret_cast<const float4*>(&Ws[(kc + kk) * M + c0]);
                float4 wb = *reinterpret_cast<const float4*>(&Ws[(kc + kk) * M + c0 + 4]);
#pragma unroll
                for (int r = 0; r < 4; r++) {
                    float xv = (&xa[r].x)[kk];
                    acc[r][0] += xv * wa.x; acc[r][1] += xv * wa.y;
                    acc[r][2] += xv * wa.z; acc[r][3] += xv * wa.w;
                    acc[r][4] += xv * wb.x; acc[r][5] += xv * wb.y;
                    acc[r][6] += xv * wb.z; acc[r][7] += xv * wb.w;
                }
            }
        }
        __syncthreads();
    }

#pragma unroll
    for (int r = 0; r < 4; r++) {
        int row = row0 + r0 + r;
        if (row < nrows) {
            *reinterpret_cast<float4*>(&out[(size_t)row * M + c0]) =
                make_float4(acc[r][0], acc[r][1], acc[r][2], acc[r][3]);
            *reinterpret_cast<float4*>(&out[(size_t)row * M + c0 + 4]) =
                make_float4(acc[r][4], acc[r][5], acc[r][6], acc[r][7]);
        }
    }
}

// ---------------- fused: agg layer0 (64f) into smem, then gemm1 (64->32) ----------------
// Block: 512 threads, 64 nodes. Agg phase: 32 groups of 16 threads, 2 passes.
// Gemm phase: threads 0-127 compute 4 rows x 4 cols each from smem h-tile.
__global__ void __launch_bounds__(512)
agg0_gemm1_kernel(const float* __restrict__ m, const float* __restrict__ b,
                  const float* __restrict__ W1, float* __restrict__ out, int n) {
    __shared__ float Hs[64 * 64];   // post-relu h tile, 16KB
    __shared__ float Ws[64 * 32];   // W1, 8KB

    int tid = threadIdx.x;
    for (int i = tid; i < 64 * 32 / 4; i += 512)
        reinterpret_cast<float4*>(Ws)[i] = reinterpret_cast<const float4*>(W1)[i];

    const float4* m4 = reinterpret_cast<const float4*>(m);
    int grp = tid >> 4;           // 0..31
    int f   = tid & 15;           // feature float4 slot
    float4 bb = reinterpret_cast<const float4*>(b)[f];

#pragma unroll
    for (int pass = 0; pass < 2; pass++) {
        int lrow = pass * 32 + grp;
        int gid = blockIdx.x * 64 + lrow;
        float4 acc;
        if (gid < n) {
            float di = g_dinv[gid];
            float ws = di * di;
            acc = m4[(size_t)gid * 16 + f];
            acc.x *= ws; acc.y *= ws; acc.z *= ws; acc.w *= ws;

            int p = g_rs[gid], p1 = g_rs[gid + 1];
            for (; p + 1 < p1; p += 2) {
                int2  c0 = g_csr[p], c1 = g_csr[p + 1];
                float w0 = __int_as_float(c0.y), w1 = __int_as_float(c1.y);
                float4 v0 = m4[(size_t)c0.x * 16 + f];
                float4 v1 = m4[(size_t)c1.x * 16 + f];
                acc.x += v0.x * w0 + v1.x * w1;
                acc.y += v0.y * w0 + v1.y * w1;
                acc.z += v0.z * w0 + v1.z * w1;
                acc.w += v0.w * w0 + v1.w * w1;
            }
            if (p < p1) {
                int2 c0 = g_csr[p];
                float w0 = __int_as_float(c0.y);
                float4 v0 = m4[(size_t)c0.x * 16 + f];
                acc.x += v0.x * w0; acc.y += v0.y * w0;
                acc.z += v0.z * w0; acc.w += v0.w * w0;
            }
            acc.x = fmaxf(acc.x + bb.x, 0.f);
            acc.y = fmaxf(acc.y + bb.y, 0.f);
            acc.z = fmaxf(acc.z + bb.z, 0.f);
            acc.w = fmaxf(acc.w + bb.w, 0.f);
        } else {
            acc = make_float4(0.f, 0.f, 0.f, 0.f);
        }
        *reinterpret_cast<float4*>(&Hs[lrow * 64 + f * 4]) = acc;
    }
    __syncthreads();

    // gemm phase: 128 threads, each 4 rows x 4 cols (64x32 tile, K=64)
    if (tid < 128) {
        int tx = tid & 7;        // 8 col groups x 4
        int ty = tid >> 3;       // 16 row groups x 4
        int c0 = tx * 4, r0 = ty * 4;

        float acc[4][4];
#pragma unroll
        for (int r = 0; r < 4; r++)
#pragma unroll
            for (int c = 0; c < 4; c++) acc[r][c] = 0.f;

#pragma unroll 4
        for (int kc = 0; kc < 64; kc += 4) {
            float4 xa[4];
#pragma unroll
            for (int r = 0; r < 4; r++)
                xa[r] = *reinterpret_cast<const float4*>(&Hs[(r0 + r) * 64 + kc]);
#pragma unroll
            for (int kk = 0; kk < 4; kk++) {
                float4 w = *reinterpret_cast<const float4*>(&Ws[(kc + kk) * 32 + c0]);
#pragma unroll
                for (int r = 0; r < 4; r++) {
                    float xv = (&xa[r].x)[kk];
                    acc[r][0] += xv * w.x; acc[r][1] += xv * w.y;
                    acc[r][2] += xv * w.z; acc[r][3] += xv * w.w;
                }
            }
        }
#pragma unroll
        for (int r = 0; r < 4; r++) {
            int row = blockIdx.x * 64 + r0 + r;
            if (row < n)
                *reinterpret_cast<float4*>(&out[(size_t)row * 32 + c0]) =
                    make_float4(acc[r][0], acc[r][1], acc[r][2], acc[r][3]);
        }
    }
}

// ---------------- CSR node aggregation (layer 1), fused self-loop + bias + relu ----------------
template <int FD4>
__global__ void node_agg_kernel(const float* __restrict__ m, const float* __restrict__ b,
                                float* __restrict__ h, int n) {
    int gid = (blockIdx.x * blockDim.x + threadIdx.x) / FD4;
    int f = threadIdx.x % FD4;
    if (gid >= n) return;
    const float4* m4 = reinterpret_cast<const float4*>(m);

    float di = g_dinv[gid];
    float ws = di * di;
    float4 acc = m4[(size_t)gid * FD4 + f];
    acc.x *= ws; acc.y *= ws; acc.z *= ws; acc.w *= ws;

    int p = g_rs[gid], p1 = g_rs[gid + 1];
    for (; p + 3 < p1; p += 4) {
        int2  c0 = g_csr[p],     c1 = g_csr[p + 1];
        int2  c2 = g_csr[p + 2], c3 = g_csr[p + 3];
        float w0 = __int_as_float(c0.y), w1 = __int_as_float(c1.y);
        float w2 = __int_as_float(c2.y), w3 = __int_as_float(c3.y);
        float4 v0 = m4[(size_t)c0.x * FD4 + f];
        float4 v1 = m4[(size_t)c1.x * FD4 + f];
        float4 v2 = m4[(size_t)c2.x * FD4 + f];
        float4 v3 = m4[(size_t)c3.x * FD4 + f];
        acc.x += v0.x * w0 + v1.x * w1 + v2.x * w2 + v3.x * w3;
        acc.y += v0.y * w0 + v1.y * w1 + v2.y * w2 + v3.y * w3;
        acc.z += v0.z * w0 + v1.z * w1 + v2.z * w2 + v3.z * w3;
        acc.w += v0.w * w0 + v1.w * w1 + v2.w * w2 + v3.w * w3;
    }
    for (; p < p1; p++) {
        int2 c0 = g_csr[p];
        float w0 = __int_as_float(c0.y);
        float4 v0 = m4[(size_t)c0.x * FD4 + f];
        acc.x += v0.x * w0; acc.y += v0.y * w0;
        acc.z += v0.z * w0; acc.w += v0.w * w0;
    }

    float4 bb = reinterpret_cast<const float4*>(b)[f];
    acc.x = fmaxf(acc.x + bb.x, 0.f);
    acc.y = fmaxf(acc.y + bb.y, 0.f);
    acc.z = fmaxf(acc.z + bb.z, 0.f);
    acc.w = fmaxf(acc.w + bb.w, 0.f);
    reinterpret_cast<float4*>(h)[(size_t)gid * FD4 + f] = acc;
}

// ---------------- fused pool + MLP ----------------
__global__ void poolmlp_kernel(const float* __restrict__ h2, const int* __restrict__ ngi,
                               const float* __restrict__ Wm1, const float* __restrict__ bm1,
                               const float* __restrict__ Wm2, const float* __restrict__ bm2,
                               float* __restrict__ out) {
    __shared__ int bounds[2];
    __shared__ float red[4][32];
    __shared__ float gs[32];
    __shared__ float g2s[128];

    int b = blockIdx.x, t = threadIdx.x;

    if (t < 2) {
        int target = b + t;            // lower_bound(ngi, target)
        int lo = 0, hi = N_NODES;
        while (lo < hi) {
            int mid = (lo + hi) >> 1;
            if (ngi[mid] < target) lo = mid + 1; else hi = mid;
        }
        bounds[t] = lo;
    }
    __syncthreads();
    int start = bounds[0], end = bounds[1];

    int lane = t & 31, r = t >> 5;
    float acc = 0.f;
    for (int i = start + r; i < end; i += 4)
        acc += h2[(size_t)i * 32 + lane];
    red[r][lane] = acc;
    __syncthreads();
    if (t < 32) gs[t] = red[0][t] + red[1][t] + red[2][t] + red[3][t];
    __syncthreads();

    float a1 = bm1[t];
#pragma unroll
    for (int k = 0; k < 32; k++) a1 += gs[k] * Wm1[k * 128 + t];
    g2s[t] = fmaxf(a1, 0.f);
    __syncthreads();
    if (t < 2) {
        float a = bm2[t];
#pragma unroll
        for (int k = 0; k < 128; k++) a += g2s[k] * Wm2[k * 2 + t];
        out[b * 2 + t] = a;
    }
}

// ---------------- host ----------------
extern "C" void kernel_launch(void* const* d_in, const int* in_sizes, int n_in,
                              void* d_out, int out_size) {
    const float* x   = (const float*)d_in[0];
    const int*   ei  = (const int*)d_in[1];
    const float* ew  = (const float*)d_in[2];
    const int*   ngi = (const int*)d_in[3];
    const float* W0  = (const float*)d_in[4];
    const float* b0  = (const float*)d_in[5];
    const float* W1  = (const float*)d_in[6];
    const float* b1  = (const float*)d_in[7];
    const float* Wm1 = (const float*)d_in[8];
    const float* bm1 = (const float*)d_in[9];
    const float* Wm2 = (const float*)d_in[10];
    const float* bm2 = (const float*)d_in[11];
    float* out = (float*)d_out;

    const int* srcp = ei;
    const int* dstp = ei + N_EDGES;

    static cudaStream_t s2 = nullptr;
    static cudaEvent_t  e_fork = nullptr, e_join = nullptr;
    if (s2 == nullptr) {
        cudaStreamCreateWithFlags(&s2, cudaStreamNonBlocking);
        cudaEventCreateWithFlags(&e_fork, cudaEventDisableTiming);
        cudaEventCreateWithFlags(&e_join, cudaEventDisableTiming);
    }

    void *p_deg, *p_cnt, *p_m, *p_m2, *p_h2;
    cudaGetSymbolAddress(&p_deg, g_deg);
    cudaGetSymbolAddress(&p_cnt, g_cnt);
    cudaGetSymbolAddress(&p_m,   g_m);
    cudaGetSymbolAddress(&p_m2,  g_m2);
    cudaGetSymbolAddress(&p_h2,  g_h2);

    // ---- fork: CSR/normalization build on s2, gemm0 on the main stream ----
    cudaEventRecord(e_fork, 0);
    cudaStreamWaitEvent(s2, e_fork, 0);

    cudaMemsetAsync(p_deg, 0, N_NODES * sizeof(float), s2);
    cudaMemsetAsync(p_cnt, 0, N_NODES * sizeof(int), s2);
    edge_prep_kernel<<<(N_EDGES + 255) / 256, 256, 0, s2>>>(dstp, ew, N_EDGES);
    dinv_scan1_kernel<<<N_SBLK, SCAN_B, 0, s2>>>(N_NODES);
    scan23_kernel<<<N_SBLK, SCAN_B, 0, s2>>>(N_NODES);
    scatter_kernel<<<(N_EDGES + 255) / 256, 256, 0, s2>>>(srcp, dstp, ew, N_EDGES);
    cudaEventRecord(e_join, s2);

    // main stream: layer-0 GEMM runs concurrently with the build
    gemm_kernel<128, 64, 64, 64><<<(N_NODES + 63) / 64, 128>>>(x, W0, (float*)p_m, N_NODES);

    // ---- join, then the serial tail ----
    cudaStreamWaitEvent(0, e_join, 0);

    agg0_gemm1_kernel<<<(N_NODES + 63) / 64, 512>>>((const float*)p_m, b0, W1, (float*)p_m2, N_NODES);
    node_agg_kernel<8><<<(N_NODES * 8 + 255) / 256, 256>>>((const float*)p_m2, b1, (float*)p_h2, N_NODES);

    poolmlp_kernel<<<N_GRAPHS, 128>>>((const float*)p_h2, ngi, Wm1, bm1, Wm2, bm2, out);
}

// round 9
// speedup vs baseline: 1.0737x; 1.0737x over previous
#include <cuda_runtime.h>
#include <cuda_bf16.h>

#define N_NODES  100000
#define N_EDGES  1600000
#define N_GRAPHS 1000
#define SCAN_B   1024
#define N_SBLK   ((N_NODES + SCAN_B - 1) / SCAN_B)   // 98

// ---------------- scratch (static __device__, no allocs) ----------------
__device__ float g_deg[N_NODES];
__device__ float g_dinv[N_NODES];
__device__ int   g_cnt[N_NODES];
__device__ int   g_rank[N_EDGES];
__device__ int   g_rs[N_NODES + 1];
__device__ int   g_bsum[N_SBLK];
__device__ int2  g_csr[N_EDGES];          // {src, weight-as-bits}
__device__ float g_m[N_NODES * 64];
__device__ float g_h[N_NODES * 64];
__device__ float g_m2[N_NODES * 32];
__device__ float g_h2[N_NODES * 32];

// ---------------- degree + in-degree count + rank capture (4 edges/thread) ----------------
__global__ void edge_prep_kernel(const int* __restrict__ dst, const float* __restrict__ w, int E) {
    int e0 = (blockIdx.x * blockDim.x + threadIdx.x) * 4;
    if (e0 + 3 >= E) {
        for (int e = e0; e < E; e++) {
            int d = dst[e];
            atomicAdd(&g_deg[d], w[e]);
            g_rank[e] = atomicAdd(&g_cnt[d], 1);
        }
        return;
    }
    int4   d4 = *reinterpret_cast<const int4*>(dst + e0);
    float4 w4 = *reinterpret_cast<const float4*>(w + e0);
    atomicAdd(&g_deg[d4.x], w4.x);
    atomicAdd(&g_deg[d4.y], w4.y);
    atomicAdd(&g_deg[d4.z], w4.z);
    atomicAdd(&g_deg[d4.w], w4.w);
    int4 r4;
    r4.x = atomicAdd(&g_cnt[d4.x], 1);
    r4.y = atomicAdd(&g_cnt[d4.y], 1);
    r4.z = atomicAdd(&g_cnt[d4.z], 1);
    r4.w = atomicAdd(&g_cnt[d4.w], 1);
    *reinterpret_cast<int4*>(g_rank + e0) = r4;
}

// ---------------- fused dinv + scan stage 1 ----------------
__global__ void dinv_scan1_kernel(int n) {
    __shared__ int wsum[32];
    int i = blockIdx.x * SCAN_B + threadIdx.x;
    int lane = threadIdx.x & 31, wid = threadIdx.x >> 5;

    if (i < n) {
        float d = g_deg[i] + 1.0f;  // self loop weight 1
        g_dinv[i] = rsqrtf(fmaxf(d, 1e-12f));
    }
    if (i == 0) g_rs[0] = 0;

    int v = (i < n) ? g_cnt[i] : 0;
    int s = v;
#pragma unroll
    for (int o = 1; o < 32; o <<= 1) {
        int t = __shfl_up_sync(0xffffffffu, s, o);
        if (lane >= o) s += t;
    }
    if (lane == 31) wsum[wid] = s;
    __syncthreads();
    if (wid == 0) {
        int ws = wsum[lane];
#pragma unroll
        for (int o = 1; o < 32; o <<= 1) {
            int t = __shfl_up_sync(0xffffffffu, ws, o);
            if (lane >= o) ws += t;
        }
        wsum[lane] = ws;
    }
    __syncthreads();
    int off = (wid > 0) ? wsum[wid - 1] : 0;
    int incl = s + off;
    if (i < n) g_rs[i + 1] = incl;
    if (threadIdx.x == SCAN_B - 1) g_bsum[blockIdx.x] = incl;
}

// ---------------- scan stage 2+3 merged ----------------
__global__ void scan23_kernel(int n) {
    __shared__ int pref;
    if (blockIdx.x == 0) return;
    if (threadIdx.x == 0) {
        int s = 0;
        for (int j = 0; j < (int)blockIdx.x; j++) s += g_bsum[j];
        pref = s;
    }
    __syncthreads();
    int i = blockIdx.x * SCAN_B + threadIdx.x;
    if (i < n) g_rs[i + 1] += pref;
}

// ---------------- scatter into CSR (atomic-free, 4 edges/thread ILP) ----------------
__global__ void scatter_kernel(const int* __restrict__ src, const int* __restrict__ dst,
                               const float* __restrict__ w, int E) {
    int e0 = (blockIdx.x * blockDim.x + threadIdx.x) * 4;
    if (e0 + 3 >= E) {
        for (int e = e0; e < E; e++) {
            int s = src[e], d = dst[e];
            int pos = g_rs[d] + g_rank[e];
            float nw = g_dinv[s] * w[e] * g_dinv[d];
            g_csr[pos] = make_int2(s, __float_as_int(nw));
        }
        return;
    }
    int4   s4 = *reinterpret_cast<const int4*>(src + e0);
    int4   d4 = *reinterpret_cast<const int4*>(dst + e0);
    int4   r4 = *reinterpret_cast<const int4*>(g_rank + e0);
    float4 w4 = *reinterpret_cast<const float4*>(w + e0);

    int p0 = g_rs[d4.x] + r4.x;
    int p1 = g_rs[d4.y] + r4.y;
    int p2 = g_rs[d4.z] + r4.z;
    int p3 = g_rs[d4.w] + r4.w;
    float n0 = g_dinv[s4.x] * w4.x * g_dinv[d4.x];
    float n1 = g_dinv[s4.y] * w4.y * g_dinv[d4.y];
    float n2 = g_dinv[s4.z] * w4.z * g_dinv[d4.z];
    float n3 = g_dinv[s4.w] * w4.w * g_dinv[d4.w];
    g_csr[p0] = make_int2(s4.x, __float_as_int(n0));
    g_csr[p1] = make_int2(s4.y, __float_as_int(n1));
    g_csr[p2] = make_int2(s4.z, __float_as_int(n2));
    g_csr[p3] = make_int2(s4.w, __float_as_int(n3));
}

// ---------------- register-blocked GEMM: out[N,M] = X[N,K] @ W[K,M] ----------------
template <int K, int M, int TR, int KP>
__global__ void __launch_bounds__(TR * M / 32)
gemm_kernel(const float* __restrict__ X, const float* __restrict__ W,
            float* __restrict__ out, int nrows) {
    __shared__ float Ws[KP * M];
    __shared__ float Xs[TR * KP];
    constexpr int T = TR * M / 32;

    int row0 = blockIdx.x * TR;
    int nr = nrows - row0; if (nr > TR) nr = TR;
    const float4* Xg = reinterpret_cast<const float4*>(X);

    int tx = threadIdx.x % (M / 8);
    int ty = threadIdx.x / (M / 8);
    int c0 = tx * 8;
    int r0 = ty * 4;

    float acc[4][8];
#pragma unroll
    for (int r = 0; r < 4; r++)
#pragma unroll
        for (int c = 0; c < 8; c++) acc[r][c] = 0.f;

    for (int ph = 0; ph < K; ph += KP) {
        for (int i = threadIdx.x; i < KP * M / 4; i += T)
            reinterpret_cast<float4*>(Ws)[i] = reinterpret_cast<const float4*>(W + ph * M)[i];
        for (int i = threadIdx.x; i < nr * (KP / 4); i += T) {
            int row = i / (KP / 4), col = i % (KP / 4);
            reinterpret_cast<float4*>(Xs)[row * (KP / 4) + col] =
                Xg[((size_t)(row0 + row) * K + ph) / 4 + col];
        }
        __syncthreads();

#pragma unroll 2
        for (int kc = 0; kc < KP; kc += 4) {
            float4 xa[4];
#pragma unroll
            for (int r = 0; r < 4; r++)
                xa[r] = *reinterpret_cast<const float4*>(&Xs[(r0 + r) * KP + kc]);
#pragma unroll
            for (int kk = 0; kk < 4; kk++) {
                float4 wa = *reinterpret_cast<const float4*>(&Ws[(kc + kk) * M + c0]);
                float4 wb = *reinterpret_cast<const float4*>(&Ws[(kc + kk) * M + c0 + 4]);
#pragma unroll
                for (int r = 0; r < 4; r++) {
                    float xv = (&xa[r].x)[kk];
                    acc[r][0] += xv * wa.x; acc[r][1] += xv * wa.y;
                    acc[r][2] += xv * wa.z; acc[r][3] += xv * wa.w;
                    acc[r][4] += xv * wb.x; acc[r][5] += xv * wb.y;
                    acc[r][6] += xv * wb.z; acc[r][7] += xv * wb.w;
                }
            }
        }
        __syncthreads();
    }

#pragma unroll
    for (int r = 0; r < 4; r++) {
        int row = row0 + r0 + r;
        if (row < nrows) {
            *reinterpret_cast<float4*>(&out[(size_t)row * M + c0]) =
                make_float4(acc[r][0], acc[r][1], acc[r][2], acc[r][3]);
            *reinterpret_cast<float4*>(&out[(size_t)row * M + c0 + 4]) =
                make_float4(acc[r][4], acc[r][5], acc[r][6], acc[r][7]);
        }
    }
}

// ---------------- CSR node aggregation, fused self-loop + bias + relu ----------------
// FD4 threads per node (float4 features each): 16 for F=64, 8 for F=32.
template <int FD4>
__global__ void node_agg_kernel(const float* __restrict__ m, const float* __restrict__ b,
                                float* __restrict__ h, int n) {
    int gid = (blockIdx.x * blockDim.x + threadIdx.x) / FD4;
    int f = threadIdx.x % FD4;
    if (gid >= n) return;
    const float4* m4 = reinterpret_cast<const float4*>(m);

    float di = g_dinv[gid];
    float ws = di * di;
    float4 acc = m4[(size_t)gid * FD4 + f];
    acc.x *= ws; acc.y *= ws; acc.z *= ws; acc.w *= ws;

    int p = g_rs[gid], p1 = g_rs[gid + 1];
    for (; p + 1 < p1; p += 2) {
        int2  c0 = g_csr[p], c1 = g_csr[p + 1];
        float w0 = __int_as_float(c0.y), w1 = __int_as_float(c1.y);
        float4 v0 = m4[(size_t)c0.x * FD4 + f];
        float4 v1 = m4[(size_t)c1.x * FD4 + f];
        acc.x += v0.x * w0 + v1.x * w1;
        acc.y += v0.y * w0 + v1.y * w1;
        acc.z += v0.z * w0 + v1.z * w1;
        acc.w += v0.w * w0 + v1.w * w1;
    }
    if (p < p1) {
        int2 c0 = g_csr[p];
        float w0 = __int_as_float(c0.y);
        float4 v0 = m4[(size_t)c0.x * FD4 + f];
        acc.x += v0.x * w0; acc.y += v0.y * w0;
        acc.z += v0.z * w0; acc.w += v0.w * w0;
    }

    float4 bb = reinterpret_cast<const float4*>(b)[f];
    acc.x = fmaxf(acc.x + bb.x, 0.f);
    acc.y = fmaxf(acc.y + bb.y, 0.f);
    acc.z = fmaxf(acc.z + bb.z, 0.f);
    acc.w = fmaxf(acc.w + bb.w, 0.f);
    reinterpret_cast<float4*>(h)[(size_t)gid * FD4 + f] = acc;
}

// ---------------- fused pool + MLP ----------------
__global__ void poolmlp_kernel(const float* __restrict__ h2, const int* __restrict__ ngi,
                               const float* __restrict__ Wm1, const float* __restrict__ bm1,
                               const float* __restrict__ Wm2, const float* __restrict__ bm2,
                               float* __restrict__ out) {
    __shared__ int bounds[2];
    __shared__ float red[4][32];
    __shared__ float gs[32];
    __shared__ float g2s[128];

    int b = blockIdx.x, t = threadIdx.x;

    if (t < 2) {
        int target = b + t;            // lower_bound(ngi, target)
        int lo = 0, hi = N_NODES;
        while (lo < hi) {
            int mid = (lo + hi) >> 1;
            if (ngi[mid] < target) lo = mid + 1; else hi = mid;
        }
        bounds[t] = lo;
    }
    __syncthreads();
    int start = bounds[0], end = bounds[1];

    int lane = t & 31, r = t >> 5;
    float acc = 0.f;
    for (int i = start + r; i < end; i += 4)
        acc += h2[(size_t)i * 32 + lane];
    red[r][lane] = acc;
    __syncthreads();
    if (t < 32) gs[t] = red[0][t] + red[1][t] + red[2][t] + red[3][t];
    __syncthreads();

    float a1 = bm1[t];
#pragma unroll
    for (int k = 0; k < 32; k++) a1 += gs[k] * Wm1[k * 128 + t];
    g2s[t] = fmaxf(a1, 0.f);
    __syncthreads();
    if (t < 2) {
        float a = bm2[t];
#pragma unroll
        for (int k = 0; k < 128; k++) a += g2s[k] * Wm2[k * 2 + t];
        out[b * 2 + t] = a;
    }
}

// ---------------- host ----------------
extern "C" void kernel_launch(void* const* d_in, const int* in_sizes, int n_in,
                              void* d_out, int out_size) {
    const float* x   = (const float*)d_in[0];
    const int*   ei  = (const int*)d_in[1];
    const float* ew  = (const float*)d_in[2];
    const int*   ngi = (const int*)d_in[3];
    const float* W0  = (const float*)d_in[4];
    const float* b0  = (const float*)d_in[5];
    const float* W1  = (const float*)d_in[6];
    const float* b1  = (const float*)d_in[7];
    const float* Wm1 = (const float*)d_in[8];
    const float* bm1 = (const float*)d_in[9];
    const float* Wm2 = (const float*)d_in[10];
    const float* bm2 = (const float*)d_in[11];
    float* out = (float*)d_out;

    const int* srcp = ei;
    const int* dstp = ei + N_EDGES;

    static cudaStream_t s2 = nullptr;
    static cudaEvent_t  e_fork = nullptr, e_join = nullptr;
    if (s2 == nullptr) {
        cudaStreamCreateWithFlags(&s2, cudaStreamNonBlocking);
        cudaEventCreateWithFlags(&e_fork, cudaEventDisableTiming);
        cudaEventCreateWithFlags(&e_join, cudaEventDisableTiming);
    }

    void *p_deg, *p_cnt, *p_m, *p_h, *p_m2, *p_h2;
    cudaGetSymbolAddress(&p_deg, g_deg);
    cudaGetSymbolAddress(&p_cnt, g_cnt);
    cudaGetSymbolAddress(&p_m,   g_m);
    cudaGetSymbolAddress(&p_h,   g_h);
    cudaGetSymbolAddress(&p_m2,  g_m2);
    cudaGetSymbolAddress(&p_h2,  g_h2);

    // ---- fork: CSR/normalization build on s2, gemm0 on the main stream ----
    cudaEventRecord(e_fork, 0);
    cudaStreamWaitEvent(s2, e_fork, 0);

    cudaMemsetAsync(p_deg, 0, N_NODES * sizeof(float), s2);
    cudaMemsetAsync(p_cnt, 0, N_NODES * sizeof(int), s2);
    edge_prep_kernel<<<(N_EDGES / 4 + 255) / 256, 256, 0, s2>>>(dstp, ew, N_EDGES);
    dinv_scan1_kernel<<<N_SBLK, SCAN_B, 0, s2>>>(N_NODES);
    scan23_kernel<<<N_SBLK, SCAN_B, 0, s2>>>(N_NODES);
    scatter_kernel<<<(N_EDGES / 4 + 255) / 256, 256, 0, s2>>>(srcp, dstp, ew, N_EDGES);
    cudaEventRecord(e_join, s2);

    // main stream: layer-0 GEMM runs concurrently with the build
    gemm_kernel<128, 64, 64, 64><<<(N_NODES + 63) / 64, 128>>>(x, W0, (float*)p_m, N_NODES);

    // ---- join, then the serial tail ----
    cudaStreamWaitEvent(0, e_join, 0);

    node_agg_kernel<16><<<(N_NODES * 16 + 255) / 256, 256>>>((const float*)p_m, b0, (float*)p_h, N_NODES);
    gemm_kernel<64, 32, 128, 32><<<(N_NODES + 127) / 128, 128>>>((const float*)p_h, W1, (float*)p_m2, N_NODES);
    node_agg_kernel<8><<<(N_NODES * 8 + 255) / 256, 256>>>((const float*)p_m2, b1, (float*)p_h2, N_NODES);

    poolmlp_kernel<<<N_GRAPHS, 128>>>((const float*)p_h2, ngi, Wm1, bm1, Wm2, bm2, out);
}

// round 10
// speedup vs baseline: 1.1804x; 1.0994x over previous
#include <cuda_runtime.h>
#include <cuda_fp16.h>

#define N_NODES  100000
#define N_EDGES  1600000
#define N_GRAPHS 1000
#define SCAN_B   1024
#define N_SBLK   ((N_NODES + SCAN_B - 1) / SCAN_B)   // 98

// ---------------- scratch (static __device__, no allocs) ----------------
__device__ float g_deg[N_NODES];
__device__ float g_dinv[N_NODES];
__device__ int   g_cnt[N_NODES];
__device__ int   g_rank[N_EDGES];
__device__ int   g_rs[N_NODES + 1];
__device__ int   g_bsum[N_SBLK];
__device__ int2  g_csr[N_EDGES];          // {src, dinv[src]*w as bits}
__device__ __align__(16) __half g_m [N_NODES * 64];  // layer0 transform, fp16
__device__ float g_h[N_NODES * 64];                  // layer0 output, fp32
__device__ __align__(16) __half g_m2[N_NODES * 32];  // layer1 transform, fp16
__device__ float g_pool[N_GRAPHS * 32];

// ---------------- degree + in-degree count + rank capture (4 edges/thread) ----------------
__global__ void edge_prep_kernel(const int* __restrict__ dst, const float* __restrict__ w, int E) {
    int e0 = (blockIdx.x * blockDim.x + threadIdx.x) * 4;
    if (e0 + 3 >= E) {
        for (int e = e0; e < E; e++) {
            int d = dst[e];
            atomicAdd(&g_deg[d], w[e]);
            g_rank[e] = atomicAdd(&g_cnt[d], 1);
        }
        return;
    }
    int4   d4 = *reinterpret_cast<const int4*>(dst + e0);
    float4 w4 = *reinterpret_cast<const float4*>(w + e0);
    atomicAdd(&g_deg[d4.x], w4.x);
    atomicAdd(&g_deg[d4.y], w4.y);
    atomicAdd(&g_deg[d4.z], w4.z);
    atomicAdd(&g_deg[d4.w], w4.w);
    int4 r4;
    r4.x = atomicAdd(&g_cnt[d4.x], 1);
    r4.y = atomicAdd(&g_cnt[d4.y], 1);
    r4.z = atomicAdd(&g_cnt[d4.z], 1);
    r4.w = atomicAdd(&g_cnt[d4.w], 1);
    *reinterpret_cast<int4*>(g_rank + e0) = r4;
}

// ---------------- fused dinv + scan stage 1 ----------------
__global__ void dinv_scan1_kernel(int n) {
    __shared__ int wsum[32];
    int i = blockIdx.x * SCAN_B + threadIdx.x;
    int lane = threadIdx.x & 31, wid = threadIdx.x >> 5;

    if (i < n) {
        float d = g_deg[i] + 1.0f;  // self loop weight 1
        g_dinv[i] = rsqrtf(fmaxf(d, 1e-12f));
    }
    if (i == 0) g_rs[0] = 0;

    int v = (i < n) ? g_cnt[i] : 0;
    int s = v;
#pragma unroll
    for (int o = 1; o < 32; o <<= 1) {
        int t = __shfl_up_sync(0xffffffffu, s, o);
        if (lane >= o) s += t;
    }
    if (lane == 31) wsum[wid] = s;
    __syncthreads();
    if (wid == 0) {
        int ws = wsum[lane];
#pragma unroll
        for (int o = 1; o < 32; o <<= 1) {
            int t = __shfl_up_sync(0xffffffffu, ws, o);
            if (lane >= o) ws += t;
        }
        wsum[lane] = ws;
    }
    __syncthreads();
    int off = (wid > 0) ? wsum[wid - 1] : 0;
    int incl = s + off;
    if (i < n) g_rs[i + 1] = incl;
    if (threadIdx.x == SCAN_B - 1) g_bsum[blockIdx.x] = incl;
}

// ---------------- scan stage 2+3 merged ----------------
__global__ void scan23_kernel(int n) {
    __shared__ int pref;
    if (blockIdx.x == 0) return;
    if (threadIdx.x == 0) {
        int s = 0;
        for (int j = 0; j < (int)blockIdx.x; j++) s += g_bsum[j];
        pref = s;
    }
    __syncthreads();
    int i = blockIdx.x * SCAN_B + threadIdx.x;
    if (i < n) g_rs[i + 1] += pref;
}

// ---------------- scatter: csr[pos] = {src, dinv[src]*w} (dst-side dinv folded out) ----------------
__global__ void scatter_kernel(const int* __restrict__ src, const int* __restrict__ dst,
                               const float* __restrict__ w, int E) {
    int e0 = (blockIdx.x * blockDim.x + threadIdx.x) * 4;
    if (e0 + 3 >= E) {
        for (int e = e0; e < E; e++) {
            int s = src[e], d = dst[e];
            int pos = g_rs[d] + g_rank[e];
            float nw = g_dinv[s] * w[e];
            g_csr[pos] = make_int2(s, __float_as_int(nw));
        }
        return;
    }
    int4   s4 = *reinterpret_cast<const int4*>(src + e0);
    int4   d4 = *reinterpret_cast<const int4*>(dst + e0);
    int4   r4 = *reinterpret_cast<const int4*>(g_rank + e0);
    float4 w4 = *reinterpret_cast<const float4*>(w + e0);

    int p0 = g_rs[d4.x] + r4.x;
    int p1 = g_rs[d4.y] + r4.y;
    int p2 = g_rs[d4.z] + r4.z;
    int p3 = g_rs[d4.w] + r4.w;
    float n0 = g_dinv[s4.x] * w4.x;
    float n1 = g_dinv[s4.y] * w4.y;
    float n2 = g_dinv[s4.z] * w4.z;
    float n3 = g_dinv[s4.w] * w4.w;
    g_csr[p0] = make_int2(s4.x, __float_as_int(n0));
    g_csr[p1] = make_int2(s4.y, __float_as_int(n1));
    g_csr[p2] = make_int2(s4.z, __float_as_int(n2));
    g_csr[p3] = make_int2(s4.w, __float_as_int(n3));
}

// ---------------- register-blocked GEMM: out[N,M] = X[N,K] @ W[K,M], fp16 output ----------------
template <int K, int M, int TR, int KP>
__global__ void __launch_bounds__(TR * M / 32)
gemm_kernel(const float* __restrict__ X, const float* __restrict__ W,
            __half* __restrict__ out, int nrows) {
    __shared__ float Ws[KP * M];
    __shared__ float Xs[TR * KP];
    constexpr int T = TR * M / 32;

    int row0 = blockIdx.x * TR;
    int nr = nrows - row0; if (nr > TR) nr = TR;
    const float4* Xg = reinterpret_cast<const float4*>(X);

    int tx = threadIdx.x % (M / 8);
    int ty = threadIdx.x / (M / 8);
    int c0 = tx * 8;
    int r0 = ty * 4;

    float acc[4][8];
#pragma unroll
    for (int r = 0; r < 4; r++)
#pragma unroll
        for (int c = 0; c < 8; c++) acc[r][c] = 0.f;

    for (int ph = 0; ph < K; ph += KP) {
        for (int i = threadIdx.x; i < KP * M / 4; i += T)
            reinterpret_cast<float4*>(Ws)[i] = reinterpret_cast<const float4*>(W + ph * M)[i];
        for (int i = threadIdx.x; i < nr * (KP / 4); i += T) {
            int row = i / (KP / 4), col = i % (KP / 4);
            reinterpret_cast<float4*>(Xs)[row * (KP / 4) + col] =
                Xg[((size_t)(row0 + row) * K + ph) / 4 + col];
        }
        __syncthreads();

#pragma unroll 2
        for (int kc = 0; kc < KP; kc += 4) {
            float4 xa[4];
#pragma unroll
            for (int r = 0; r < 4; r++)
                xa[r] = *reinterpret_cast<const float4*>(&Xs[(r0 + r) * KP + kc]);
#pragma unroll
            for (int kk = 0; kk < 4; kk++) {
                float4 wa = *reinterpret_cast<const float4*>(&Ws[(kc + kk) * M + c0]);
                float4 wb = *reinterpret_cast<const float4*>(&Ws[(kc + kk) * M + c0 + 4]);
#pragma unroll
                for (int r = 0; r < 4; r++) {
                    float xv = (&xa[r].x)[kk];
                    acc[r][0] += xv * wa.x; acc[r][1] += xv * wa.y;
                    acc[r][2] += xv * wa.z; acc[r][3] += xv * wa.w;
                    acc[r][4] += xv * wb.x; acc[r][5] += xv * wb.y;
                    acc[r][6] += xv * wb.z; acc[r][7] += xv * wb.w;
                }
            }
        }
        __syncthreads();
    }

#pragma unroll
    for (int r = 0; r < 4; r++) {
        int row = row0 + r0 + r;
        if (row < nrows) {
            __align__(16) __half2 hs[4];
            hs[0] = __float22half2_rn(make_float2(acc[r][0], acc[r][1]));
            hs[1] = __float22half2_rn(make_float2(acc[r][2], acc[r][3]));
            hs[2] = __float22half2_rn(make_float2(acc[r][4], acc[r][5]));
            hs[3] = __float22half2_rn(make_float2(acc[r][6], acc[r][7]));
            *reinterpret_cast<uint4*>(&out[(size_t)row * M + c0]) =
                *reinterpret_cast<uint4*>(hs);
        }
    }
}

// ---------------- agg layer0: h = relu(dinv_d*(sum nw*m[s] + dinv_d*m[d]) + b), fp16 in, fp32 out ----
// 8 threads/node, each owns 8 features (one uint4 = 8 halves per gather).
__global__ void node_agg0_kernel(const __half* __restrict__ m, const float* __restrict__ b,
                                 float* __restrict__ h, int n) {
    int gid = (blockIdx.x * blockDim.x + threadIdx.x) >> 3;
    int ft = threadIdx.x & 7;
    if (gid >= n) return;
    const uint4* m4 = reinterpret_cast<const uint4*>(m);   // row stride 8 uint4

    float acc[8];
    float di = g_dinv[gid];
    {
        uint4 raw = m4[(size_t)gid * 8 + ft];
        const __half2* hp = reinterpret_cast<const __half2*>(&raw);
#pragma unroll
        for (int j = 0; j < 4; j++) {
            float2 v = __half22float2(hp[j]);
            acc[j * 2 + 0] = di * v.x;
            acc[j * 2 + 1] = di * v.y;
        }
    }

    int p = g_rs[gid], p1 = g_rs[gid + 1];
    for (; p + 1 < p1; p += 2) {
        int2 c0 = g_csr[p], c1 = g_csr[p + 1];
        float w0 = __int_as_float(c0.y), w1 = __int_as_float(c1.y);
        uint4 r0 = m4[(size_t)c0.x * 8 + ft];
        uint4 r1 = m4[(size_t)c1.x * 8 + ft];
        const __half2* h0 = reinterpret_cast<const __half2*>(&r0);
        const __half2* h1 = reinterpret_cast<const __half2*>(&r1);
#pragma unroll
        for (int j = 0; j < 4; j++) {
            float2 v0 = __half22float2(h0[j]);
            float2 v1 = __half22float2(h1[j]);
            acc[j * 2 + 0] += v0.x * w0 + v1.x * w1;
            acc[j * 2 + 1] += v0.y * w0 + v1.y * w1;
        }
    }
    if (p < p1) {
        int2 c0 = g_csr[p];
        float w0 = __int_as_float(c0.y);
        uint4 r0 = m4[(size_t)c0.x * 8 + ft];
        const __half2* h0 = reinterpret_cast<const __half2*>(&r0);
#pragma unroll
        for (int j = 0; j < 4; j++) {
            float2 v0 = __half22float2(h0[j]);
            acc[j * 2 + 0] += v0.x * w0;
            acc[j * 2 + 1] += v0.y * w0;
        }
    }

    float4 o0, o1;
    const float* bp = b + ft * 8;
    o0.x = fmaxf(acc[0] * di + bp[0], 0.f);
    o0.y = fmaxf(acc[1] * di + bp[1], 0.f);
    o0.z = fmaxf(acc[2] * di + bp[2], 0.f);
    o0.w = fmaxf(acc[3] * di + bp[3], 0.f);
    o1.x = fmaxf(acc[4] * di + bp[4], 0.f);
    o1.y = fmaxf(acc[5] * di + bp[5], 0.f);
    o1.z = fmaxf(acc[6] * di + bp[6], 0.f);
    o1.w = fmaxf(acc[7] * di + bp[7], 0.f);
    float* hp = h + (size_t)gid * 64 + ft * 8;
    *reinterpret_cast<float4*>(hp)     = o0;
    *reinterpret_cast<float4*>(hp + 4) = o1;
}

// ---------------- agg layer1 + fused pooling: red h2 rows straight into g_pool ----------------
// 4 threads/node, each owns 8 features.
__global__ void node_agg1_pool_kernel(const __half* __restrict__ m, const float* __restrict__ b,
                                      const int* __restrict__ ngi, int n) {
    int gid = (blockIdx.x * blockDim.x + threadIdx.x) >> 2;
    int ft = threadIdx.x & 3;
    if (gid >= n) return;
    const uint4* m4 = reinterpret_cast<const uint4*>(m);   // row stride 4 uint4

    float acc[8];
    float di = g_dinv[gid];
    {
        uint4 raw = m4[(size_t)gid * 4 + ft];
        const __half2* hp = reinterpret_cast<const __half2*>(&raw);
#pragma unroll
        for (int j = 0; j < 4; j++) {
            float2 v = __half22float2(hp[j]);
            acc[j * 2 + 0] = di * v.x;
            acc[j * 2 + 1] = di * v.y;
        }
    }

    int p = g_rs[gid], p1 = g_rs[gid + 1];
    for (; p + 1 < p1; p += 2) {
        int2 c0 = g_csr[p], c1 = g_csr[p + 1];
        float w0 = __int_as_float(c0.y), w1 = __int_as_float(c1.y);
        uint4 r0 = m4[(size_t)c0.x * 4 + ft];
        uint4 r1 = m4[(size_t)c1.x * 4 + ft];
        const __half2* h0 = reinterpret_cast<const __half2*>(&r0);
        const __half2* h1 = reinterpret_cast<const __half2*>(&r1);
#pragma unroll
        for (int j = 0; j < 4; j++) {
            float2 v0 = __half22float2(h0[j]);
            float2 v1 = __half22float2(h1[j]);
            acc[j * 2 + 0] += v0.x * w0 + v1.x * w1;
            acc[j * 2 + 1] += v0.y * w0 + v1.y * w1;
        }
    }
    if (p < p1) {
        int2 c0 = g_csr[p];
        float w0 = __int_as_float(c0.y);
        uint4 r0 = m4[(size_t)c0.x * 4 + ft];
        const __half2* h0 = reinterpret_cast<const __half2*>(&r0);
#pragma unroll
        for (int j = 0; j < 4; j++) {
            float2 v0 = __half22float2(h0[j]);
            acc[j * 2 + 0] += v0.x * w0;
            acc[j * 2 + 1] += v0.y * w0;
        }
    }

    const float* bp = b + ft * 8;
    float v0 = fmaxf(acc[0] * di + bp[0], 0.f);
    float v1 = fmaxf(acc[1] * di + bp[1], 0.f);
    float v2 = fmaxf(acc[2] * di + bp[2], 0.f);
    float v3 = fmaxf(acc[3] * di + bp[3], 0.f);
    float v4 = fmaxf(acc[4] * di + bp[4], 0.f);
    float v5 = fmaxf(acc[5] * di + bp[5], 0.f);
    float v6 = fmaxf(acc[6] * di + bp[6], 0.f);
    float v7 = fmaxf(acc[7] * di + bp[7], 0.f);

    int graph = ngi[gid];
    float* pp = &g_pool[graph * 32 + ft * 8];
    asm volatile("red.global.add.v4.f32 [%0], {%1, %2, %3, %4};"
                 :: "l"(pp), "f"(v0), "f"(v1), "f"(v2), "f"(v3) : "memory");
    asm volatile("red.global.add.v4.f32 [%0], {%1, %2, %3, %4};"
                 :: "l"(pp + 4), "f"(v4), "f"(v5), "f"(v6), "f"(v7) : "memory");
}

// ---------------- MLP head on pooled features ----------------
__global__ void mlp_kernel(const float* __restrict__ Wm1, const float* __restrict__ bm1,
                           const float* __restrict__ Wm2, const float* __restrict__ bm2,
                           float* __restrict__ out) {
    __shared__ float gs[32];
    __shared__ float g2s[128];
    int b = blockIdx.x, t = threadIdx.x;
    if (t < 32) gs[t] = g_pool[b * 32 + t];
    __syncthreads();
    float a1 = bm1[t];
#pragma unroll
    for (int k = 0; k < 32; k++) a1 += gs[k] * Wm1[k * 128 + t];
    g2s[t] = fmaxf(a1, 0.f);
    __syncthreads();
    if (t < 2) {
        float a = bm2[t];
#pragma unroll
        for (int k = 0; k < 128; k++) a += g2s[k] * Wm2[k * 2 + t];
        out[b * 2 + t] = a;
    }
}

// ---------------- host ----------------
extern "C" void kernel_launch(void* const* d_in, const int* in_sizes, int n_in,
                              void* d_out, int out_size) {
    const float* x   = (const float*)d_in[0];
    const int*   ei  = (const int*)d_in[1];
    const float* ew  = (const float*)d_in[2];
    const int*   ngi = (const int*)d_in[3];
    const float* W0  = (const float*)d_in[4];
    const float* b0  = (const float*)d_in[5];
    const float* W1  = (const float*)d_in[6];
    const float* b1  = (const float*)d_in[7];
    const float* Wm1 = (const float*)d_in[8];
    const float* bm1 = (const float*)d_in[9];
    const float* Wm2 = (const float*)d_in[10];
    const float* bm2 = (const float*)d_in[11];
    float* out = (float*)d_out;

    const int* srcp = ei;
    const int* dstp = ei + N_EDGES;

    static cudaStream_t s2 = nullptr;
    static cudaEvent_t  e_fork = nullptr, e_join = nullptr;
    if (s2 == nullptr) {
        cudaStreamCreateWithFlags(&s2, cudaStreamNonBlocking);
        cudaEventCreateWithFlags(&e_fork, cudaEventDisableTiming);
        cudaEventCreateWithFlags(&e_join, cudaEventDisableTiming);
    }

    void *p_deg, *p_cnt, *p_pool, *p_m, *p_h, *p_m2;
    cudaGetSymbolAddress(&p_deg,  g_deg);
    cudaGetSymbolAddress(&p_cnt,  g_cnt);
    cudaGetSymbolAddress(&p_pool, g_pool);
    cudaGetSymbolAddress(&p_m,    g_m);
    cudaGetSymbolAddress(&p_h,    g_h);
    cudaGetSymbolAddress(&p_m2,   g_m2);

    // ---- fork: CSR/normalization build on s2, gemm0 on the main stream ----
    cudaEventRecord(e_fork, 0);
    cudaStreamWaitEvent(s2, e_fork, 0);

    cudaMemsetAsync(p_deg,  0, N_NODES * sizeof(float), s2);
    cudaMemsetAsync(p_cnt,  0, N_NODES * sizeof(int), s2);
    cudaMemsetAsync(p_pool, 0, N_GRAPHS * 32 * sizeof(float), s2);
    edge_prep_kernel<<<(N_EDGES / 4 + 255) / 256, 256, 0, s2>>>(dstp, ew, N_EDGES);
    dinv_scan1_kernel<<<N_SBLK, SCAN_B, 0, s2>>>(N_NODES);
    scan23_kernel<<<N_SBLK, SCAN_B, 0, s2>>>(N_NODES);
    scatter_kernel<<<(N_EDGES / 4 + 255) / 256, 256, 0, s2>>>(srcp, dstp, ew, N_EDGES);
    cudaEventRecord(e_join, s2);

    // main stream: layer-0 GEMM (fp16 output) runs concurrently with the build
    gemm_kernel<128, 64, 64, 64><<<(N_NODES + 63) / 64, 128>>>(x, W0, (__half*)p_m, N_NODES);

    // ---- join, then the serial tail ----
    cudaStreamWaitEvent(0, e_join, 0);

    node_agg0_kernel<<<(N_NODES * 8 + 255) / 256, 256>>>((const __half*)p_m, b0, (float*)p_h, N_NODES);
    gemm_kernel<64, 32, 128, 32><<<(N_NODES + 127) / 128, 128>>>((const float*)p_h, W1, (__half*)p_m2, N_NODES);
    node_agg1_pool_kernel<<<(N_NODES * 4 + 255) / 256, 256>>>((const __half*)p_m2, b1, ngi, N_NODES);

    mlp_kernel<<<N_GRAPHS, 128>>>(Wm1, bm1, Wm2, bm2, out);
}

// round 12
// speedup vs baseline: 1.2273x; 1.0397x over previous
#include <cuda_runtime.h>
#include <cuda_fp16.h>
#include <cstdint>

#define N_NODES  100000
#define N_EDGES  1600000
#define N_GRAPHS 1000
#define SCAN_B   1024
#define N_SBLK   ((N_NODES + SCAN_B - 1) / SCAN_B)   // 98

// ---------------- scratch (static __device__, no allocs) ----------------
// g_deg / g_cnt / g_pool are zeroed at module load and re-zeroed by the tail
// of every launch (mlp_kernel cleanup), so no memsets are needed per launch.
__device__ float g_deg[N_NODES];
__device__ float g_dinv[N_NODES];
__device__ int   g_cnt[N_NODES];
__device__ int   g_rank[N_EDGES];
__device__ int   g_rs[N_NODES + 1];
__device__ int   g_bsum[N_SBLK];
__device__ int2  g_csr[N_EDGES];          // {src, dinv[src]*w as bits}
__device__ __align__(16) __half g_m [N_NODES * 64];  // layer0 transform, fp16
__device__ float g_h[N_NODES * 64];                  // layer0 output, fp32
__device__ __align__(16) __half g_m2[N_NODES * 32];  // layer1 transform, fp16
__device__ float g_pool[N_GRAPHS * 32];

// ---------------- degree + in-degree count + rank capture (4 edges/thread) ----------------
__global__ void edge_prep_kernel(const int* __restrict__ dst, const float* __restrict__ w, int E) {
    int e0 = (blockIdx.x * blockDim.x + threadIdx.x) * 4;
    if (e0 + 3 >= E) {
        for (int e = e0; e < E; e++) {
            int d = dst[e];
            atomicAdd(&g_deg[d], w[e]);
            g_rank[e] = atomicAdd(&g_cnt[d], 1);
        }
        return;
    }
    int4   d4 = *reinterpret_cast<const int4*>(dst + e0);
    float4 w4 = *reinterpret_cast<const float4*>(w + e0);
    atomicAdd(&g_deg[d4.x], w4.x);
    atomicAdd(&g_deg[d4.y], w4.y);
    atomicAdd(&g_deg[d4.z], w4.z);
    atomicAdd(&g_deg[d4.w], w4.w);
    int4 r4;
    r4.x = atomicAdd(&g_cnt[d4.x], 1);
    r4.y = atomicAdd(&g_cnt[d4.y], 1);
    r4.z = atomicAdd(&g_cnt[d4.z], 1);
    r4.w = atomicAdd(&g_cnt[d4.w], 1);
    *reinterpret_cast<int4*>(g_rank + e0) = r4;
}

// ---------------- fused dinv + scan stage 1 ----------------
__global__ void dinv_scan1_kernel(int n) {
    __shared__ int wsum[32];
    int i = blockIdx.x * SCAN_B + threadIdx.x;
    int lane = threadIdx.x & 31, wid = threadIdx.x >> 5;

    if (i < n) {
        float d = g_deg[i] + 1.0f;  // self loop weight 1
        g_dinv[i] = rsqrtf(fmaxf(d, 1e-12f));
    }
    if (i == 0) g_rs[0] = 0;

    int v = (i < n) ? g_cnt[i] : 0;
    int s = v;
#pragma unroll
    for (int o = 1; o < 32; o <<= 1) {
        int t = __shfl_up_sync(0xffffffffu, s, o);
        if (lane >= o) s += t;
    }
    if (lane == 31) wsum[wid] = s;
    __syncthreads();
    if (wid == 0) {
        int ws = wsum[lane];
#pragma unroll
        for (int o = 1; o < 32; o <<= 1) {
            int t = __shfl_up_sync(0xffffffffu, ws, o);
            if (lane >= o) ws += t;
        }
        wsum[lane] = ws;
    }
    __syncthreads();
    int off = (wid > 0) ? wsum[wid - 1] : 0;
    int incl = s + off;
    if (i < n) g_rs[i + 1] = incl;
    if (threadIdx.x == SCAN_B - 1) g_bsum[blockIdx.x] = incl;
}

// ---------------- scan stage 2+3 merged ----------------
__global__ void scan23_kernel(int n) {
    __shared__ int pref;
    if (blockIdx.x == 0) return;
    if (threadIdx.x == 0) {
        int s = 0;
        for (int j = 0; j < (int)blockIdx.x; j++) s += g_bsum[j];
        pref = s;
    }
    __syncthreads();
    int i = blockIdx.x * SCAN_B + threadIdx.x;
    if (i < n) g_rs[i + 1] += pref;
}

// ---------------- scatter: csr[pos] = {src, dinv[src]*w} ----------------
__global__ void scatter_kernel(const int* __restrict__ src, const int* __restrict__ dst,
                               const float* __restrict__ w, int E) {
    int e0 = (blockIdx.x * blockDim.x + threadIdx.x) * 4;
    if (e0 + 3 >= E) {
        for (int e = e0; e < E; e++) {
            int s = src[e], d = dst[e];
            int pos = g_rs[d] + g_rank[e];
            float nw = g_dinv[s] * w[e];
            g_csr[pos] = make_int2(s, __float_as_int(nw));
        }
        return;
    }
    int4   s4 = *reinterpret_cast<const int4*>(src + e0);
    int4   d4 = *reinterpret_cast<const int4*>(dst + e0);
    int4   r4 = *reinterpret_cast<const int4*>(g_rank + e0);
    float4 w4 = *reinterpret_cast<const float4*>(w + e0);

    int p0 = g_rs[d4.x] + r4.x;
    int p1 = g_rs[d4.y] + r4.y;
    int p2 = g_rs[d4.z] + r4.z;
    int p3 = g_rs[d4.w] + r4.w;
    float n0 = g_dinv[s4.x] * w4.x;
    float n1 = g_dinv[s4.y] * w4.y;
    float n2 = g_dinv[s4.z] * w4.z;
    float n3 = g_dinv[s4.w] * w4.w;
    g_csr[p0] = make_int2(s4.x, __float_as_int(n0));
    g_csr[p1] = make_int2(s4.y, __float_as_int(n1));
    g_csr[p2] = make_int2(s4.z, __float_as_int(n2));
    g_csr[p3] = make_int2(s4.w, __float_as_int(n3));
}

// ---------------- tf32 tensor-core GEMM: out[N,M] = X[N,K] @ W[K,M], fp16 out ----------------
// 128 threads (4 warps), TR=64 rows/block. Warp w: rows 16w..16w+15, all M cols.
// mma.sync.m16n8k8.tf32, f32 accumulate. smem staged as pre-converted tf32 bits.
__device__ __forceinline__ uint32_t f2tf32(float x) {
    uint32_t u;
    asm("cvt.rna.tf32.f32 %0, %1;" : "=r"(u) : "f"(x));
    return u;
}

template <int K, int M, int TR, int KP>
__global__ void __launch_bounds__(128)
gemm_tf32_kernel(const float* __restrict__ X, const float* __restrict__ W,
                 __half* __restrict__ out, int nrows) {
    constexpr int XS = KP + 4;          // padded strides (bank-conflict-free A frags)
    constexpr int WS = M + 4;
    __shared__ uint32_t Xs[TR * XS];
    __shared__ uint32_t Ws[KP * WS];

    int row0 = blockIdx.x * TR;
    int nr = nrows - row0; if (nr > TR) nr = TR;
    int tid = threadIdx.x;
    int warp = tid >> 5, lane = tid & 31;
    int lg = lane >> 2, lt = lane & 3;   // group row / in-group col

    float acc[M / 8][4];
#pragma unroll
    for (int nt = 0; nt < M / 8; nt++)
#pragma unroll
        for (int j = 0; j < 4; j++) acc[nt][j] = 0.f;

    for (int ph = 0; ph < K; ph += KP) {
        for (int i = tid; i < KP * M; i += 128) {
            int r = i / M, c = i % M;
            Ws[r * WS + c] = f2tf32(W[(size_t)(ph + r) * M + c]);
        }
        for (int i = tid; i < nr * KP; i += 128) {
            int r = i / KP, c = i % KP;
            Xs[r * XS + c] = f2tf32(X[(size_t)(row0 + r) * K + ph + c]);
        }
        __syncthreads();

        int R = warp * 16;
#pragma unroll
        for (int kc = 0; kc < KP; kc += 8) {
            uint32_t a0 = Xs[(R + lg) * XS + kc + lt];
            uint32_t a1 = Xs[(R + lg + 8) * XS + kc + lt];
            uint32_t a2 = Xs[(R + lg) * XS + kc + lt + 4];
            uint32_t a3 = Xs[(R + lg + 8) * XS + kc + lt + 4];
#pragma unroll
            for (int nt = 0; nt < M / 8; nt++) {
                uint32_t b0 = Ws[(kc + lt) * WS + nt * 8 + lg];
                uint32_t b1 = Ws[(kc + lt + 4) * WS + nt * 8 + lg];
                asm volatile(
                    "mma.sync.aligned.m16n8k8.row.col.f32.tf32.tf32.f32 "
                    "{%0,%1,%2,%3}, {%4,%5,%6,%7}, {%8,%9}, {%0,%1,%2,%3};"
                    : "+f"(acc[nt][0]), "+f"(acc[nt][1]), "+f"(acc[nt][2]), "+f"(acc[nt][3])
                    : "r"(a0), "r"(a1), "r"(a2), "r"(a3), "r"(b0), "r"(b1));
            }
        }
        __syncthreads();
    }

    // store fp16: thread owns cols {2*lt, 2*lt+1} of rows (R+lg) and (R+lg+8) per n-tile
    int r_lo = row0 + warp * 16 + lg;
    int r_hi = r_lo + 8;
#pragma unroll
    for (int nt = 0; nt < M / 8; nt++) {
        if (r_lo < nrows) {
            __half2 v = __floats2half2_rn(acc[nt][0], acc[nt][1]);
            reinterpret_cast<__half2*>(out + (size_t)r_lo * M)[nt * 4 + lt] = v;
        }
        if (r_hi < nrows) {
            __half2 v = __floats2half2_rn(acc[nt][2], acc[nt][3]);
            reinterpret_cast<__half2*>(out + (size_t)r_hi * M)[nt * 4 + lt] = v;
        }
    }
}

// ---------------- agg layer0: h = relu(di*(sum nw*m[s] + di*m[d]) + b), fp16 in, fp32 out ----
// 8 threads/node, each owns 8 features (one uint4 = 8 halves per gather).
__global__ void node_agg0_kernel(const __half* __restrict__ m, const float* __restrict__ b,
                                 float* __restrict__ h, int n) {
    int gid = (blockIdx.x * blockDim.x + threadIdx.x) >> 3;
    int ft = threadIdx.x & 7;
    if (gid >= n) return;
    const uint4* m4 = reinterpret_cast<const uint4*>(m);   // row stride 8 uint4

    float acc[8];
    float di = g_dinv[gid];
    {
        uint4 raw = m4[(size_t)gid * 8 + ft];
        const __half2* hp = reinterpret_cast<const __half2*>(&raw);
#pragma unroll
        for (int j = 0; j < 4; j++) {
            float2 v = __half22float2(hp[j]);
            acc[j * 2 + 0] = di * v.x;
            acc[j * 2 + 1] = di * v.y;
        }
    }

    int p = g_rs[gid], p1 = g_rs[gid + 1];
    for (; p + 1 < p1; p += 2) {
        int2 c0 = g_csr[p], c1 = g_csr[p + 1];
        float w0 = __int_as_float(c0.y), w1 = __int_as_float(c1.y);
        uint4 r0 = m4[(size_t)c0.x * 8 + ft];
        uint4 r1 = m4[(size_t)c1.x * 8 + ft];
        const __half2* h0 = reinterpret_cast<const __half2*>(&r0);
        const __half2* h1 = reinterpret_cast<const __half2*>(&r1);
#pragma unroll
        for (int j = 0; j < 4; j++) {
            float2 v0 = __half22float2(h0[j]);
            float2 v1 = __half22float2(h1[j]);
            acc[j * 2 + 0] += v0.x * w0 + v1.x * w1;
            acc[j * 2 + 1] += v0.y * w0 + v1.y * w1;
        }
    }
    if (p < p1) {
        int2 c0 = g_csr[p];
        float w0 = __int_as_float(c0.y);
        uint4 r0 = m4[(size_t)c0.x * 8 + ft];
        const __half2* h0 = reinterpret_cast<const __half2*>(&r0);
#pragma unroll
        for (int j = 0; j < 4; j++) {
            float2 v0 = __half22float2(h0[j]);
            acc[j * 2 + 0] += v0.x * w0;
            acc[j * 2 + 1] += v0.y * w0;
        }
    }

    float4 o0, o1;
    const float* bp = b + ft * 8;
    o0.x = fmaxf(acc[0] * di + bp[0], 0.f);
    o0.y = fmaxf(acc[1] * di + bp[1], 0.f);
    o0.z = fmaxf(acc[2] * di + bp[2], 0.f);
    o0.w = fmaxf(acc[3] * di + bp[3], 0.f);
    o1.x = fmaxf(acc[4] * di + bp[4], 0.f);
    o1.y = fmaxf(acc[5] * di + bp[5], 0.f);
    o1.z = fmaxf(acc[6] * di + bp[6], 0.f);
    o1.w = fmaxf(acc[7] * di + bp[7], 0.f);
    float* hp = h + (size_t)gid * 64 + ft * 8;
    *reinterpret_cast<float4*>(hp)     = o0;
    *reinterpret_cast<float4*>(hp + 4) = o1;
}

// ---------------- agg layer1 + fused pooling into g_pool ----------------
__global__ void node_agg1_pool_kernel(const __half* __restrict__ m, const float* __restrict__ b,
                                      const int* __restrict__ ngi, int n) {
    int gid = (blockIdx.x * blockDim.x + threadIdx.x) >> 2;
    int ft = threadIdx.x & 3;
    if (gid >= n) return;
    const uint4* m4 = reinterpret_cast<const uint4*>(m);   // row stride 4 uint4

    float acc[8];
    float di = g_dinv[gid];
    {
        uint4 raw = m4[(size_t)gid * 4 + ft];
        const __half2* hp = reinterpret_cast<const __half2*>(&raw);
#pragma unroll
        for (int j = 0; j < 4; j++) {
            float2 v = __half22float2(hp[j]);
            acc[j * 2 + 0] = di * v.x;
            acc[j * 2 + 1] = di * v.y;
        }
    }

    int p = g_rs[gid], p1 = g_rs[gid + 1];
    for (; p + 1 < p1; p += 2) {
        int2 c0 = g_csr[p], c1 = g_csr[p + 1];
        float w0 = __int_as_float(c0.y), w1 = __int_as_float(c1.y);
        uint4 r0 = m4[(size_t)c0.x * 4 + ft];
        uint4 r1 = m4[(size_t)c1.x * 4 + ft];
        const __half2* h0 = reinterpret_cast<const __half2*>(&r0);
        const __half2* h1 = reinterpret_cast<const __half2*>(&r1);
#pragma unroll
        for (int j = 0; j < 4; j++) {
            float2 v0 = __half22float2(h0[j]);
            float2 v1 = __half22float2(h1[j]);
            acc[j * 2 + 0] += v0.x * w0 + v1.x * w1;
            acc[j * 2 + 1] += v0.y * w0 + v1.y * w1;
        }
    }
    if (p < p1) {
        int2 c0 = g_csr[p];
        float w0 = __int_as_float(c0.y);
        uint4 r0 = m4[(size_t)c0.x * 4 + ft];
        const __half2* h0 = reinterpret_cast<const __half2*>(&r0);
#pragma unroll
        for (int j = 0; j < 4; j++) {
            float2 v0 = __half22float2(h0[j]);
            acc[j * 2 + 0] += v0.x * w0;
            acc[j * 2 + 1] += v0.y * w0;
        }
    }

    const float* bp = b + ft * 8;
    float v0 = fmaxf(acc[0] * di + bp[0], 0.f);
    float v1 = fmaxf(acc[1] * di + bp[1], 0.f);
    float v2 = fmaxf(acc[2] * di + bp[2], 0.f);
    float v3 = fmaxf(acc[3] * di + bp[3], 0.f);
    float v4 = fmaxf(acc[4] * di + bp[4], 0.f);
    float v5 = fmaxf(acc[5] * di + bp[5], 0.f);
    float v6 = fmaxf(acc[6] * di + bp[6], 0.f);
    float v7 = fmaxf(acc[7] * di + bp[7], 0.f);

    int graph = ngi[gid];
    float* pp = &g_pool[graph * 32 + ft * 8];
    asm volatile("red.global.add.v4.f32 [%0], {%1, %2, %3, %4};"
                 :: "l"(pp), "f"(v0), "f"(v1), "f"(v2), "f"(v3) : "memory");
    asm volatile("red.global.add.v4.f32 [%0], {%1, %2, %3, %4};"
                 :: "l"(pp + 4), "f"(v4), "f"(v5), "f"(v6), "f"(v7) : "memory");
}

// ---------------- MLP head + scratch cleanup for the next replay ----------------
__global__ void mlp_kernel(const float* __restrict__ Wm1, const float* __restrict__ bm1,
                           const float* __restrict__ Wm2, const float* __restrict__ bm2,
                           float* __restrict__ out) {
    __shared__ float gs[32];
    __shared__ float g2s[128];
    int b = blockIdx.x, t = threadIdx.x;

    // cleanup: zero deg/cnt for the next launch (128K threads cover 100K entries)
    int idx = b * 128 + t;
    if (idx < N_NODES) { g_deg[idx] = 0.f; g_cnt[idx] = 0; }

    if (t < 32) {
        gs[t] = g_pool[b * 32 + t];
        g_pool[b * 32 + t] = 0.f;      // same thread read-then-zero: safe
    }
    __syncthreads();
    float a1 = bm1[t];
#pragma unroll
    for (int k = 0; k < 32; k++) a1 += gs[k] * Wm1[k * 128 + t];
    g2s[t] = fmaxf(a1, 0.f);
    __syncthreads();
    if (t < 2) {
        float a = bm2[t];
#pragma unroll
        for (int k = 0; k < 128; k++) a += g2s[k] * Wm2[k * 2 + t];
        out[b * 2 + t] = a;
    }
}

// ---------------- host ----------------
extern "C" void kernel_launch(void* const* d_in, const int* in_sizes, int n_in,
                              void* d_out, int out_size) {
    const float* x   = (const float*)d_in[0];
    const int*   ei  = (const int*)d_in[1];
    const float* ew  = (const float*)d_in[2];
    const int*   ngi = (const int*)d_in[3];
    const float* W0  = (const float*)d_in[4];
    const float* b0  = (const float*)d_in[5];
    const float* W1  = (const float*)d_in[6];
    const float* b1  = (const float*)d_in[7];
    const float* Wm1 = (const float*)d_in[8];
    const float* bm1 = (const float*)d_in[9];
    const float* Wm2 = (const float*)d_in[10];
    const float* bm2 = (const float*)d_in[11];
    float* out = (float*)d_out;

    const int* srcp = ei;
    const int* dstp = ei + N_EDGES;

    static cudaStream_t s2 = nullptr;
    static cudaEvent_t  e_fork = nullptr, e_join = nullptr;
    if (s2 == nullptr) {
        cudaStreamCreateWithFlags(&s2, cudaStreamNonBlocking);
        cudaEventCreateWithFlags(&e_fork, cudaEventDisableTiming);
        cudaEventCreateWithFlags(&e_join, cudaEventDisableTiming);
    }

    void *p_m, *p_h, *p_m2;
    cudaGetSymbolAddress(&p_m,  g_m);
    cudaGetSymbolAddress(&p_h,  g_h);
    cudaGetSymbolAddress(&p_m2, g_m2);

    // ---- fork: CSR/normalization build on s2, gemm0 on the main stream ----
    cudaEventRecord(e_fork, 0);
    cudaStreamWaitEvent(s2, e_fork, 0);

    edge_prep_kernel<<<(N_EDGES / 4 + 255) / 256, 256, 0, s2>>>(dstp, ew, N_EDGES);
    dinv_scan1_kernel<<<N_SBLK, SCAN_B, 0, s2>>>(N_NODES);
    scan23_kernel<<<N_SBLK, SCAN_B, 0, s2>>>(N_NODES);
    scatter_kernel<<<(N_EDGES / 4 + 255) / 256, 256, 0, s2>>>(srcp, dstp, ew, N_EDGES);
    cudaEventRecord(e_join, s2);

    // main stream: layer-0 GEMM (tf32 tensor cores, fp16 output) concurrent with build
    gemm_tf32_kernel<128, 64, 64, 64><<<(N_NODES + 63) / 64, 128>>>(x, W0, (__half*)p_m, N_NODES);

    // ---- join, then the serial tail ----
    cudaStreamWaitEvent(0, e_join, 0);

    node_agg0_kernel<<<(N_NODES * 8 + 255) / 256, 256>>>((const __half*)p_m, b0, (float*)p_h, N_NODES);
    gemm_tf32_kernel<64, 32, 64, 64><<<(N_NODES + 63) / 64, 128>>>((const float*)p_h, W1, (__half*)p_m2, N_NODES);
    node_agg1_pool_kernel<<<(N_NODES * 4 + 255) / 256, 256>>>((const __half*)p_m2, b1, ngi, N_NODES);

    mlp_kernel<<<N_GRAPHS, 128>>>(Wm1, bm1, Wm2, bm2, out);
}

// round 13
// speedup vs baseline: 1.3565x; 1.1052x over previous
#include <cuda_runtime.h>
#include <cuda_fp16.h>
#include <cstdint>

#define N_NODES  100000
#define N_EDGES  1600000
#define N_GRAPHS 1000
#define SCAN_B   1024
#define N_SBLK   ((N_NODES + SCAN_B - 1) / SCAN_B)   // 98

// ---------------- scratch (static __device__, no allocs) ----------------
// g_cnt / g_pool are zeroed at module load and re-zeroed by mlp_kernel's
// cleanup each launch, so no per-launch memsets are needed.
__device__ float g_dinv[N_NODES];
__device__ int   g_cnt[N_NODES];
__device__ int   g_rank[N_EDGES];
__device__ int   g_rs[N_NODES + 1];
__device__ int   g_bsum[N_SBLK];
__device__ int2  g_csr[N_EDGES];          // {src, raw w as bits}
__device__ __align__(16) __half g_m [N_NODES * 64];  // layer0 transform (pre-scaled by dinv)
__device__ __align__(16) __half g_h [N_NODES * 64];  // layer0 output, fp16
__device__ __align__(16) __half g_m2[N_NODES * 32];  // layer1 transform (pre-scaled by dinv)
__device__ float g_pool[N_GRAPHS * 32];

// ---------------- in-degree count + rank capture (4 edges/thread) ----------------
__global__ void edge_prep_kernel(const int* __restrict__ dst, int E) {
    int e0 = (blockIdx.x * blockDim.x + threadIdx.x) * 4;
    if (e0 + 3 >= E) {
        for (int e = e0; e < E; e++)
            g_rank[e] = atomicAdd(&g_cnt[dst[e]], 1);
        return;
    }
    int4 d4 = *reinterpret_cast<const int4*>(dst + e0);
    int4 r4;
    r4.x = atomicAdd(&g_cnt[d4.x], 1);
    r4.y = atomicAdd(&g_cnt[d4.y], 1);
    r4.z = atomicAdd(&g_cnt[d4.z], 1);
    r4.w = atomicAdd(&g_cnt[d4.w], 1);
    *reinterpret_cast<int4*>(g_rank + e0) = r4;
}

// ---------------- scan stage 1 ----------------
__global__ void scan1_kernel(int n) {
    __shared__ int wsum[32];
    int i = blockIdx.x * SCAN_B + threadIdx.x;
    int lane = threadIdx.x & 31, wid = threadIdx.x >> 5;
    if (i == 0) g_rs[0] = 0;

    int v = (i < n) ? g_cnt[i] : 0;
    int s = v;
#pragma unroll
    for (int o = 1; o < 32; o <<= 1) {
        int t = __shfl_up_sync(0xffffffffu, s, o);
        if (lane >= o) s += t;
    }
    if (lane == 31) wsum[wid] = s;
    __syncthreads();
    if (wid == 0) {
        int ws = wsum[lane];
#pragma unroll
        for (int o = 1; o < 32; o <<= 1) {
            int t = __shfl_up_sync(0xffffffffu, ws, o);
            if (lane >= o) ws += t;
        }
        wsum[lane] = ws;
    }
    __syncthreads();
    int off = (wid > 0) ? wsum[wid - 1] : 0;
    int incl = s + off;
    if (i < n) g_rs[i + 1] = incl;
    if (threadIdx.x == SCAN_B - 1) g_bsum[blockIdx.x] = incl;
}

// ---------------- scan stage 2+3 merged ----------------
__global__ void scan23_kernel(int n) {
    __shared__ int pref;
    if (blockIdx.x == 0) return;
    if (threadIdx.x == 0) {
        int s = 0;
        for (int j = 0; j < (int)blockIdx.x; j++) s += g_bsum[j];
        pref = s;
    }
    __syncthreads();
    int i = blockIdx.x * SCAN_B + threadIdx.x;
    if (i < n) g_rs[i + 1] += pref;
}

// ---------------- scatter: csr[pos] = {src, raw w} over [begin, end) ----------------
__global__ void scatter_kernel(const int* __restrict__ src, const int* __restrict__ dst,
                               const float* __restrict__ w, int begin, int end) {
    int e0 = begin + (blockIdx.x * blockDim.x + threadIdx.x) * 4;
    if (e0 >= end) return;
    if (e0 + 3 >= end) {
        for (int e = e0; e < end; e++) {
            int pos = g_rs[dst[e]] + g_rank[e];
            g_csr[pos] = make_int2(src[e], __float_as_int(w[e]));
        }
        return;
    }
    int4   s4 = *reinterpret_cast<const int4*>(src + e0);
    int4   d4 = *reinterpret_cast<const int4*>(dst + e0);
    int4   r4 = *reinterpret_cast<const int4*>(g_rank + e0);
    float4 w4 = *reinterpret_cast<const float4*>(w + e0);

    g_csr[g_rs[d4.x] + r4.x] = make_int2(s4.x, __float_as_int(w4.x));
    g_csr[g_rs[d4.y] + r4.y] = make_int2(s4.y, __float_as_int(w4.y));
    g_csr[g_rs[d4.z] + r4.z] = make_int2(s4.z, __float_as_int(w4.z));
    g_csr[g_rs[d4.w] + r4.w] = make_int2(s4.w, __float_as_int(w4.w));
}

// ---------------- deg + dinv from the CSR (sequential csr reads) ----------------
__global__ void degdinv_kernel(int n) {
    int i = blockIdx.x * blockDim.x + threadIdx.x;
    if (i >= n) return;
    float s = 1.0f;                 // self loop weight
    int p1 = g_rs[i + 1];
    for (int p = g_rs[i]; p < p1; p++)
        s += __int_as_float(g_csr[p].y);
    g_dinv[i] = rsqrtf(fmaxf(s, 1e-12f));
}

// ---------------- tf32 tensor-core GEMM: out[N,M] = X[N,K] @ W[K,M], fp16 out ----------------
// Optional epilogue: scale each output row by g_dinv[row] (SCALE=true).
__device__ __forceinline__ uint32_t f2tf32(float x) {
    uint32_t u;
    asm("cvt.rna.tf32.f32 %0, %1;" : "=r"(u) : "f"(x));
    return u;
}

template <typename T, int K, int M, int TR, int KP, bool SCALE>
__global__ void __launch_bounds__(128)
gemm_tf32_kernel(const T* __restrict__ X, const float* __restrict__ W,
                 __half* __restrict__ out, int nrows) {
    constexpr int XS = KP + 4;
    constexpr int WS = M + 4;
    __shared__ uint32_t Xs[TR * XS];
    __shared__ uint32_t Ws[KP * WS];

    int row0 = blockIdx.x * TR;
    int nr = nrows - row0; if (nr > TR) nr = TR;
    int tid = threadIdx.x;
    int warp = tid >> 5, lane = tid & 31;
    int lg = lane >> 2, lt = lane & 3;

    float acc[M / 8][4];
#pragma unroll
    for (int nt = 0; nt < M / 8; nt++)
#pragma unroll
        for (int j = 0; j < 4; j++) acc[nt][j] = 0.f;

    for (int ph = 0; ph < K; ph += KP) {
        for (int i = tid; i < KP * M; i += 128) {
            int r = i / M, c = i % M;
            Ws[r * WS + c] = f2tf32(W[(size_t)(ph + r) * M + c]);
        }
        for (int i = tid; i < nr * KP; i += 128) {
            int r = i / KP, c = i % KP;
            Xs[r * XS + c] = f2tf32((float)X[(size_t)(row0 + r) * K + ph + c]);
        }
        __syncthreads();

        int R = warp * 16;
#pragma unroll
        for (int kc = 0; kc < KP; kc += 8) {
            uint32_t a0 = Xs[(R + lg) * XS + kc + lt];
            uint32_t a1 = Xs[(R + lg + 8) * XS + kc + lt];
            uint32_t a2 = Xs[(R + lg) * XS + kc + lt + 4];
            uint32_t a3 = Xs[(R + lg + 8) * XS + kc + lt + 4];
#pragma unroll
            for (int nt = 0; nt < M / 8; nt++) {
                uint32_t b0 = Ws[(kc + lt) * WS + nt * 8 + lg];
                uint32_t b1 = Ws[(kc + lt + 4) * WS + nt * 8 + lg];
                asm volatile(
                    "mma.sync.aligned.m16n8k8.row.col.f32.tf32.tf32.f32 "
                    "{%0,%1,%2,%3}, {%4,%5,%6,%7}, {%8,%9}, {%0,%1,%2,%3};"
                    : "+f"(acc[nt][0]), "+f"(acc[nt][1]), "+f"(acc[nt][2]), "+f"(acc[nt][3])
                    : "r"(a0), "r"(a1), "r"(a2), "r"(a3), "r"(b0), "r"(b1));
            }
        }
        __syncthreads();
    }

    int r_lo = row0 + warp * 16 + lg;
    int r_hi = r_lo + 8;
    float dlo = 1.f, dhi = 1.f;
    if (SCALE) {
        dlo = (r_lo < nrows) ? g_dinv[r_lo] : 0.f;
        dhi = (r_hi < nrows) ? g_dinv[r_hi] : 0.f;
    }
#pragma unroll
    for (int nt = 0; nt < M / 8; nt++) {
        if (r_lo < nrows) {
            __half2 v = __floats2half2_rn(acc[nt][0] * dlo, acc[nt][1] * dlo);
            reinterpret_cast<__half2*>(out + (size_t)r_lo * M)[nt * 4 + lt] = v;
        }
        if (r_hi < nrows) {
            __half2 v = __floats2half2_rn(acc[nt][2] * dhi, acc[nt][3] * dhi);
            reinterpret_cast<__half2*>(out + (size_t)r_hi * M)[nt * 4 + lt] = v;
        }
    }
}

// ---------------- scale m by dinv (m' = dinv[node] * m), in place, fp16 ----------------
__global__ void scale_m_kernel(__half* __restrict__ m) {
    int idx = blockIdx.x * blockDim.x + threadIdx.x;   // uint4 index (8 halves)
    if (idx >= N_NODES * 8) return;
    float di = g_dinv[idx >> 3];
    uint4 raw = reinterpret_cast<uint4*>(m)[idx];
    __half2* hp = reinterpret_cast<__half2*>(&raw);
#pragma unroll
    for (int j = 0; j < 4; j++) {
        float2 v = __half22float2(hp[j]);
        hp[j] = __floats2half2_rn(v.x * di, v.y * di);
    }
    reinterpret_cast<uint4*>(m)[idx] = raw;
}

// ---------------- agg layer0: h = relu(di*(m'[d] + sum w*m'[s]) + b), fp16 in/out ----------------
// 8 threads/node, each owns 8 features.
__global__ void node_agg0_kernel(const __half* __restrict__ m, const float* __restrict__ b,
                                 __half* __restrict__ h, int n) {
    int gid = (blockIdx.x * blockDim.x + threadIdx.x) >> 3;
    int ft = threadIdx.x & 7;
    if (gid >= n) return;
    const uint4* m4 = reinterpret_cast<const uint4*>(m);   // row stride 8 uint4

    float acc[8];
    {
        uint4 raw = m4[(size_t)gid * 8 + ft];
        const __half2* hp = reinterpret_cast<const __half2*>(&raw);
#pragma unroll
        for (int j = 0; j < 4; j++) {
            float2 v = __half22float2(hp[j]);
            acc[j * 2 + 0] = v.x;
            acc[j * 2 + 1] = v.y;
        }
    }

    int p = g_rs[gid], p1 = g_rs[gid + 1];
    for (; p + 1 < p1; p += 2) {
        int2 c0 = g_csr[p], c1 = g_csr[p + 1];
        float w0 = __int_as_float(c0.y), w1 = __int_as_float(c1.y);
        uint4 r0 = m4[(size_t)c0.x * 8 + ft];
        uint4 r1 = m4[(size_t)c1.x * 8 + ft];
        const __half2* h0 = reinterpret_cast<const __half2*>(&r0);
        const __half2* h1 = reinterpret_cast<const __half2*>(&r1);
#pragma unroll
        for (int j = 0; j < 4; j++) {
            float2 v0 = __half22float2(h0[j]);
            float2 v1 = __half22float2(h1[j]);
            acc[j * 2 + 0] += v0.x * w0 + v1.x * w1;
            acc[j * 2 + 1] += v0.y * w0 + v1.y * w1;
        }
    }
    if (p < p1) {
        int2 c0 = g_csr[p];
        float w0 = __int_as_float(c0.y);
        uint4 r0 = m4[(size_t)c0.x * 8 + ft];
        const __half2* h0 = reinterpret_cast<const __half2*>(&r0);
#pragma unroll
        for (int j = 0; j < 4; j++) {
            float2 v0 = __half22float2(h0[j]);
            acc[j * 2 + 0] += v0.x * w0;
            acc[j * 2 + 1] += v0.y * w0;
        }
    }

    float di = g_dinv[gid];
    const float* bp = b + ft * 8;
    __align__(16) __half2 o[4];
#pragma unroll
    for (int j = 0; j < 4; j++) {
        float r0 = fmaxf(acc[j * 2 + 0] * di + bp[j * 2 + 0], 0.f);
        float r1 = fmaxf(acc[j * 2 + 1] * di + bp[j * 2 + 1], 0.f);
        o[j] = __floats2half2_rn(r0, r1);
    }
    *reinterpret_cast<uint4*>(h + (size_t)gid * 64 + ft * 8) = *reinterpret_cast<uint4*>(o);
}

// ---------------- agg layer1 + fused pooling into g_pool ----------------
// 4 threads/node, each owns 8 features.
__global__ void node_agg1_pool_kernel(const __half* __restrict__ m, const float* __restrict__ b,
                                      const int* __restrict__ ngi, int n) {
    int gid = (blockIdx.x * blockDim.x + threadIdx.x) >> 2;
    int ft = threadIdx.x & 3;
    if (gid >= n) return;
    const uint4* m4 = reinterpret_cast<const uint4*>(m);   // row stride 4 uint4

    float acc[8];
    {
        uint4 raw = m4[(size_t)gid * 4 + ft];
        const __half2* hp = reinterpret_cast<const __half2*>(&raw);
#pragma unroll
        for (int j = 0; j < 4; j++) {
            float2 v = __half22float2(hp[j]);
            acc[j * 2 + 0] = v.x;
            acc[j * 2 + 1] = v.y;
        }
    }

    int p = g_rs[gid], p1 = g_rs[gid + 1];
    for (; p + 1 < p1; p += 2) {
        int2 c0 = g_csr[p], c1 = g_csr[p + 1];
        float w0 = __int_as_float(c0.y), w1 = __int_as_float(c1.y);
        uint4 r0 = m4[(size_t)c0.x * 4 + ft];
        uint4 r1 = m4[(size_t)c1.x * 4 + ft];
        const __half2* h0 = reinterpret_cast<const __half2*>(&r0);
        const __half2* h1 = reinterpret_cast<const __half2*>(&r1);
#pragma unroll
        for (int j = 0; j < 4; j++) {
            float2 v0 = __half22float2(h0[j]);
            float2 v1 = __half22float2(h1[j]);
            acc[j * 2 + 0] += v0.x * w0 + v1.x * w1;
            acc[j * 2 + 1] += v0.y * w0 + v1.y * w1;
        }
    }
    if (p < p1) {
        int2 c0 = g_csr[p];
        float w0 = __int_as_float(c0.y);
        uint4 r0 = m4[(size_t)c0.x * 4 + ft];
        const __half2* h0 = reinterpret_cast<const __half2*>(&r0);
#pragma unroll
        for (int j = 0; j < 4; j++) {
            float2 v0 = __half22float2(h0[j]);
            acc[j * 2 + 0] += v0.x * w0;
            acc[j * 2 + 1] += v0.y * w0;
        }
    }

    float di = g_dinv[gid];
    const float* bp = b + ft * 8;
    float v0 = fmaxf(acc[0] * di + bp[0], 0.f);
    float v1 = fmaxf(acc[1] * di + bp[1], 0.f);
    float v2 = fmaxf(acc[2] * di + bp[2], 0.f);
    float v3 = fmaxf(acc[3] * di + bp[3], 0.f);
    float v4 = fmaxf(acc[4] * di + bp[4], 0.f);
    float v5 = fmaxf(acc[5] * di + bp[5], 0.f);
    float v6 = fmaxf(acc[6] * di + bp[6], 0.f);
    float v7 = fmaxf(acc[7] * di + bp[7], 0.f);

    int graph = ngi[gid];
    float* pp = &g_pool[graph * 32 + ft * 8];
    asm volatile("red.global.add.v4.f32 [%0], {%1, %2, %3, %4};"
                 :: "l"(pp), "f"(v0), "f"(v1), "f"(v2), "f"(v3) : "memory");
    asm volatile("red.global.add.v4.f32 [%0], {%1, %2, %3, %4};"
                 :: "l"(pp + 4), "f"(v4), "f"(v5), "f"(v6), "f"(v7) : "memory");
}

// ---------------- MLP head + scratch cleanup for the next replay ----------------
__global__ void mlp_kernel(const float* __restrict__ Wm1, const float* __restrict__ bm1,
                           const float* __restrict__ Wm2, const float* __restrict__ bm2,
                           float* __restrict__ out) {
    __shared__ float gs[32];
    __shared__ float g2s[128];
    int b = blockIdx.x, t = threadIdx.x;

    // cleanup: zero cnt for the next launch (128K threads cover 100K entries)
    int idx = b * 128 + t;
    if (idx < N_NODES) g_cnt[idx] = 0;

    if (t < 32) {
        gs[t] = g_pool[b * 32 + t];
        g_pool[b * 32 + t] = 0.f;      // same thread read-then-zero: safe
    }
    __syncthreads();
    float a1 = bm1[t];
#pragma unroll
    for (int k = 0; k < 32; k++) a1 += gs[k] * Wm1[k * 128 + t];
    g2s[t] = fmaxf(a1, 0.f);
    __syncthreads();
    if (t < 2) {
        float a = bm2[t];
#pragma unroll
        for (int k = 0; k < 128; k++) a += g2s[k] * Wm2[k * 2 + t];
        out[b * 2 + t] = a;
    }
}

// ---------------- host ----------------
extern "C" void kernel_launch(void* const* d_in, const int* in_sizes, int n_in,
                              void* d_out, int out_size) {
    const float* x   = (const float*)d_in[0];
    const int*   ei  = (const int*)d_in[1];
    const float* ew  = (const float*)d_in[2];
    const int*   ngi = (const int*)d_in[3];
    const float* W0  = (const float*)d_in[4];
    const float* b0  = (const float*)d_in[5];
    const float* W1  = (const float*)d_in[6];
    const float* b1  = (const float*)d_in[7];
    const float* Wm1 = (const float*)d_in[8];
    const float* bm1 = (const float*)d_in[9];
    const float* Wm2 = (const float*)d_in[10];
    const float* bm2 = (const float*)d_in[11];
    float* out = (float*)d_out;

    const int* srcp = ei;
    const int* dstp = ei + N_EDGES;

    static cudaStream_t s2 = nullptr;
    static cudaEvent_t  e_fork = nullptr, e_scan = nullptr, e_sc1 = nullptr, e_join = nullptr;
    if (s2 == nullptr) {
        cudaStreamCreateWithFlags(&s2, cudaStreamNonBlocking);
        cudaEventCreateWithFlags(&e_fork, cudaEventDisableTiming);
        cudaEventCreateWithFlags(&e_scan, cudaEventDisableTiming);
        cudaEventCreateWithFlags(&e_sc1,  cudaEventDisableTiming);
        cudaEventCreateWithFlags(&e_join, cudaEventDisableTiming);
    }

    void *p_m, *p_h, *p_m2;
    cudaGetSymbolAddress(&p_m,  g_m);
    cudaGetSymbolAddress(&p_h,  g_h);
    cudaGetSymbolAddress(&p_m2, g_m2);

    const int EH = N_EDGES / 2;            // 800000, divisible by 4

    // ---- fork ----
    cudaEventRecord(e_fork, 0);
    cudaStreamWaitEvent(s2, e_fork, 0);

    // s2: count/rank + scan
    edge_prep_kernel<<<(N_EDGES / 4 + 255) / 256, 256, 0, s2>>>(dstp, N_EDGES);
    scan1_kernel<<<N_SBLK, SCAN_B, 0, s2>>>(N_NODES);
    scan23_kernel<<<N_SBLK, SCAN_B, 0, s2>>>(N_NODES);
    cudaEventRecord(e_scan, s2);

    // main: layer-0 GEMM concurrent with the scan chain, then scatter half B
    gemm_tf32_kernel<float, 128, 64, 64, 64, false>
        <<<(N_NODES + 63) / 64, 128>>>(x, W0, (__half*)p_m, N_NODES);
    cudaStreamWaitEvent(0, e_scan, 0);
    scatter_kernel<<<(EH / 4 + 255) / 256, 256>>>(srcp, dstp, ew, EH, N_EDGES);
    cudaEventRecord(e_sc1, 0);

    // s2: scatter half A, then deg+dinv after both halves
    scatter_kernel<<<(EH / 4 + 255) / 256, 256, 0, s2>>>(srcp, dstp, ew, 0, EH);
    cudaStreamWaitEvent(s2, e_sc1, 0);
    degdinv_kernel<<<(N_NODES + 255) / 256, 256, 0, s2>>>(N_NODES);
    cudaEventRecord(e_join, s2);

    // ---- join, then the serial tail on main ----
    cudaStreamWaitEvent(0, e_join, 0);

    scale_m_kernel<<<(N_NODES * 8 + 255) / 256, 256>>>((__half*)p_m);
    node_agg0_kernel<<<(N_NODES * 8 + 255) / 256, 256>>>((const __half*)p_m, b0, (__half*)p_h, N_NODES);
    gemm_tf32_kernel<__half, 64, 32, 64, 64, true>
        <<<(N_NODES + 63) / 64, 128>>>((const __half*)p_h, W1, (__half*)p_m2, N_NODES);
    node_agg1_pool_kernel<<<(N_NODES * 4 + 255) / 256, 256>>>((const __half*)p_m2, b1, ngi, N_NODES);

    mlp_kernel<<<N_GRAPHS, 128>>>(Wm1, bm1, Wm2, bm2, out);
}

// round 14
// speedup vs baseline: 1.6437x; 1.2117x over previous
#include <cuda_runtime.h>
#include <cuda_fp16.h>
#include <cstdint>

#define N_NODES  100000
#define N_EDGES  1600000
#define N_GRAPHS 1000
#define SCAN_B   1024
#define N_SBLK   ((N_NODES + SCAN_B - 1) / SCAN_B)   // 98

// ---------------- scratch (static __device__, no allocs) ----------------
__device__ float g_dinv[N_NODES];
__device__ int   g_cnt[N_NODES];
__device__ int   g_rank[N_EDGES];
__device__ int   g_rs[N_NODES + 1];
__device__ int   g_bsum[N_SBLK];
__device__ int2  g_csr[N_EDGES];          // {src, raw w as bits}
__device__ __align__(16) __half g_m [N_NODES * 64];  // layer0 transform (pre-scaled by dinv)
__device__ __align__(16) __half g_h [N_NODES * 64];  // layer0 output, fp16
__device__ __align__(16) __half g_m2[N_NODES * 32];  // layer1 transform (pre-scaled by dinv)
__device__ float g_pool[N_GRAPHS * 32];

// ---------------- in-degree count + rank capture (4 edges/thread) ----------------
__global__ void edge_prep_kernel(const int* __restrict__ dst, int E) {
    int e0 = (blockIdx.x * blockDim.x + threadIdx.x) * 4;
    if (e0 + 3 >= E) {
        for (int e = e0; e < E; e++)
            g_rank[e] = atomicAdd(&g_cnt[dst[e]], 1);
        return;
    }
    int4 d4 = *reinterpret_cast<const int4*>(dst + e0);
    int4 r4;
    r4.x = atomicAdd(&g_cnt[d4.x], 1);
    r4.y = atomicAdd(&g_cnt[d4.y], 1);
    r4.z = atomicAdd(&g_cnt[d4.z], 1);
    r4.w = atomicAdd(&g_cnt[d4.w], 1);
    *reinterpret_cast<int4*>(g_rank + e0) = r4;
}

// ---------------- scan stage 1 ----------------
__global__ void scan1_kernel(int n) {
    __shared__ int wsum[32];
    int i = blockIdx.x * SCAN_B + threadIdx.x;
    int lane = threadIdx.x & 31, wid = threadIdx.x >> 5;
    if (i == 0) g_rs[0] = 0;

    int v = (i < n) ? g_cnt[i] : 0;
    int s = v;
#pragma unroll
    for (int o = 1; o < 32; o <<= 1) {
        int t = __shfl_up_sync(0xffffffffu, s, o);
        if (lane >= o) s += t;
    }
    if (lane == 31) wsum[wid] = s;
    __syncthreads();
    if (wid == 0) {
        int ws = wsum[lane];
#pragma unroll
        for (int o = 1; o < 32; o <<= 1) {
            int t = __shfl_up_sync(0xffffffffu, ws, o);
            if (lane >= o) ws += t;
        }
        wsum[lane] = ws;
    }
    __syncthreads();
    int off = (wid > 0) ? wsum[wid - 1] : 0;
    int incl = s + off;
    if (i < n) g_rs[i + 1] = incl;
    if (threadIdx.x == SCAN_B - 1) g_bsum[blockIdx.x] = incl;
}

// ---------------- scan stage 2+3 merged ----------------
__global__ void scan23_kernel(int n) {
    __shared__ int pref;
    if (blockIdx.x == 0) return;
    if (threadIdx.x == 0) {
        int s = 0;
        for (int j = 0; j < (int)blockIdx.x; j++) s += g_bsum[j];
        pref = s;
    }
    __syncthreads();
    int i = blockIdx.x * SCAN_B + threadIdx.x;
    if (i < n) g_rs[i + 1] += pref;
}

// ---------------- scatter: csr[pos] = {src, raw w} over [begin, end) ----------------
__global__ void scatter_kernel(const int* __restrict__ src, const int* __restrict__ dst,
                               const float* __restrict__ w, int begin, int end) {
    int e0 = begin + (blockIdx.x * blockDim.x + threadIdx.x) * 4;
    if (e0 >= end) return;
    if (e0 + 3 >= end) {
        for (int e = e0; e < end; e++) {
            int pos = g_rs[dst[e]] + g_rank[e];
            g_csr[pos] = make_int2(src[e], __float_as_int(w[e]));
        }
        return;
    }
    int4   s4 = *reinterpret_cast<const int4*>(src + e0);
    int4   d4 = *reinterpret_cast<const int4*>(dst + e0);
    int4   r4 = *reinterpret_cast<const int4*>(g_rank + e0);
    float4 w4 = *reinterpret_cast<const float4*>(w + e0);

    g_csr[g_rs[d4.x] + r4.x] = make_int2(s4.x, __float_as_int(w4.x));
    g_csr[g_rs[d4.y] + r4.y] = make_int2(s4.y, __float_as_int(w4.y));
    g_csr[g_rs[d4.z] + r4.z] = make_int2(s4.z, __float_as_int(w4.z));
    g_csr[g_rs[d4.w] + r4.w] = make_int2(s4.w, __float_as_int(w4.w));
}

// ---------------- deg + dinv from the CSR (sequential csr reads) ----------------
__global__ void degdinv_kernel(int n) {
    int i = blockIdx.x * blockDim.x + threadIdx.x;
    if (i >= n) return;
    float s = 1.0f;                 // self loop weight
    int p1 = g_rs[i + 1];
    for (int p = g_rs[i]; p < p1; p++)
        s += __int_as_float(g_csr[p].y);
    g_dinv[i] = rsqrtf(fmaxf(s, 1e-12f));
}

// ---------------- tf32 tensor-core GEMM: out[N,M] = X[N,K] @ W[K,M], fp16 out ----------------
__device__ __forceinline__ uint32_t f2tf32(float x) {
    uint32_t u;
    asm("cvt.rna.tf32.f32 %0, %1;" : "=r"(u) : "f"(x));
    return u;
}

// 8-wide vector loads (16B-aligned) for float / half inputs
__device__ __forceinline__ void load8(const float* p, float* v) {
    float4 a = *reinterpret_cast<const float4*>(p);
    float4 b = *reinterpret_cast<const float4*>(p + 4);
    v[0] = a.x; v[1] = a.y; v[2] = a.z; v[3] = a.w;
    v[4] = b.x; v[5] = b.y; v[6] = b.z; v[7] = b.w;
}
__device__ __forceinline__ void load8(const __half* p, float* v) {
    uint4 raw = *reinterpret_cast<const uint4*>(p);
    const __half2* hp = reinterpret_cast<const __half2*>(&raw);
#pragma unroll
    for (int j = 0; j < 4; j++) {
        float2 f = __half22float2(hp[j]);
        v[j * 2 + 0] = f.x;
        v[j * 2 + 1] = f.y;
    }
}

// 256 threads (8 warps), TR=128 rows/block; warp w owns rows 16w..16w+15.
// XS = KP+4 (A LDS conflict-free), WS = M+8 (B LDS conflict-free: WS ≡ 8 mod 32).
template <typename T, int K, int M, int TR, int KP, bool SCALE>
__global__ void __launch_bounds__(256)
gemm_tf32_kernel(const T* __restrict__ X, const float* __restrict__ W,
                 __half* __restrict__ out, int nrows) {
    constexpr int XS = KP + 4;
    constexpr int WS = M + 8;
    __shared__ __align__(16) uint32_t Xs[TR * XS];
    __shared__ __align__(16) uint32_t Ws[KP * WS];

    int row0 = blockIdx.x * TR;
    int nr = nrows - row0; if (nr > TR) nr = TR;
    int tid = threadIdx.x;
    int warp = tid >> 5, lane = tid & 31;
    int lg = lane >> 2, lt = lane & 3;

    float acc[M / 8][4];
#pragma unroll
    for (int nt = 0; nt < M / 8; nt++)
#pragma unroll
        for (int j = 0; j < 4; j++) acc[nt][j] = 0.f;

    for (int ph = 0; ph < K; ph += KP) {
        // stage W (8 elems / iter, vectorized)
        for (int i = tid; i < KP * M / 8; i += 256) {
            int r = i / (M / 8), c8 = (i % (M / 8)) * 8;
            float v[8];
            load8(W + (size_t)(ph + r) * M + c8, v);
            uint32_t t[8];
#pragma unroll
            for (int j = 0; j < 8; j++) t[j] = f2tf32(v[j]);
            *reinterpret_cast<uint4*>(&Ws[r * WS + c8]) = make_uint4(t[0], t[1], t[2], t[3]);
            *reinterpret_cast<uint4*>(&Ws[r * WS + c8 + 4]) = make_uint4(t[4], t[5], t[6], t[7]);
        }
        // stage X (8 elems / iter, vectorized)
        for (int i = tid; i < nr * (KP / 8); i += 256) {
            int r = i / (KP / 8), c8 = (i % (KP / 8)) * 8;
            float v[8];
            load8(X + (size_t)(row0 + r) * K + ph + c8, v);
            uint32_t t[8];
#pragma unroll
            for (int j = 0; j < 8; j++) t[j] = f2tf32(v[j]);
            *reinterpret_cast<uint4*>(&Xs[r * XS + c8]) = make_uint4(t[0], t[1], t[2], t[3]);
            *reinterpret_cast<uint4*>(&Xs[r * XS + c8 + 4]) = make_uint4(t[4], t[5], t[6], t[7]);
        }
        __syncthreads();

        int R = warp * 16;
#pragma unroll
        for (int kc = 0; kc < KP; kc += 8) {
            uint32_t a0 = Xs[(R + lg) * XS + kc + lt];
            uint32_t a1 = Xs[(R + lg + 8) * XS + kc + lt];
            uint32_t a2 = Xs[(R + lg) * XS + kc + lt + 4];
            uint32_t a3 = Xs[(R + lg + 8) * XS + kc + lt + 4];
#pragma unroll
            for (int nt = 0; nt < M / 8; nt++) {
                uint32_t b0 = Ws[(kc + lt) * WS + nt * 8 + lg];
                uint32_t b1 = Ws[(kc + lt + 4) * WS + nt * 8 + lg];
                asm volatile(
                    "mma.sync.aligned.m16n8k8.row.col.f32.tf32.tf32.f32 "
                    "{%0,%1,%2,%3}, {%4,%5,%6,%7}, {%8,%9}, {%0,%1,%2,%3};"
                    : "+f"(acc[nt][0]), "+f"(acc[nt][1]), "+f"(acc[nt][2]), "+f"(acc[nt][3])
                    : "r"(a0), "r"(a1), "r"(a2), "r"(a3), "r"(b0), "r"(b1));
            }
        }
        __syncthreads();
    }

    int r_lo = row0 + warp * 16 + lg;
    int r_hi = r_lo + 8;
    float dlo = 1.f, dhi = 1.f;
    if (SCALE) {
        dlo = (r_lo < nrows) ? g_dinv[r_lo] : 0.f;
        dhi = (r_hi < nrows) ? g_dinv[r_hi] : 0.f;
    }
#pragma unroll
    for (int nt = 0; nt < M / 8; nt++) {
        if (r_lo < nrows) {
            __half2 v = __floats2half2_rn(acc[nt][0] * dlo, acc[nt][1] * dlo);
            reinterpret_cast<__half2*>(out + (size_t)r_lo * M)[nt * 4 + lt] = v;
        }
        if (r_hi < nrows) {
            __half2 v = __floats2half2_rn(acc[nt][2] * dhi, acc[nt][3] * dhi);
            reinterpret_cast<__half2*>(out + (size_t)r_hi * M)[nt * 4 + lt] = v;
        }
    }
}

// ---------------- scale m by dinv (m' = dinv[node] * m), in place, fp16 ----------------
__global__ void scale_m_kernel(__half* __restrict__ m) {
    int idx = blockIdx.x * blockDim.x + threadIdx.x;   // uint4 index (8 halves)
    if (idx >= N_NODES * 8) return;
    float di = g_dinv[idx >> 3];
    uint4 raw = reinterpret_cast<uint4*>(m)[idx];
    __half2* hp = reinterpret_cast<__half2*>(&raw);
#pragma unroll
    for (int j = 0; j < 4; j++) {
        float2 v = __half22float2(hp[j]);
        hp[j] = __floats2half2_rn(v.x * di, v.y * di);
    }
    reinterpret_cast<uint4*>(m)[idx] = raw;
}

// ---------------- agg layer0: h = relu(di*(m'[d] + sum w*m'[s]) + b), fp16 in/out ----------------
__global__ void node_agg0_kernel(const __half* __restrict__ m, const float* __restrict__ b,
                                 __half* __restrict__ h, int n) {
    int gid = (blockIdx.x * blockDim.x + threadIdx.x) >> 3;
    int ft = threadIdx.x & 7;
    if (gid >= n) return;
    const uint4* m4 = reinterpret_cast<const uint4*>(m);   // row stride 8 uint4

    float acc[8];
    {
        uint4 raw = m4[(size_t)gid * 8 + ft];
        const __half2* hp = reinterpret_cast<const __half2*>(&raw);
#pragma unroll
        for (int j = 0; j < 4; j++) {
            float2 v = __half22float2(hp[j]);
            acc[j * 2 + 0] = v.x;
            acc[j * 2 + 1] = v.y;
        }
    }

    int p = g_rs[gid], p1 = g_rs[gid + 1];
    for (; p + 1 < p1; p += 2) {
        int2 c0 = g_csr[p], c1 = g_csr[p + 1];
        float w0 = __int_as_float(c0.y), w1 = __int_as_float(c1.y);
        uint4 r0 = m4[(size_t)c0.x * 8 + ft];
        uint4 r1 = m4[(size_t)c1.x * 8 + ft];
        const __half2* h0 = reinterpret_cast<const __half2*>(&r0);
        const __half2* h1 = reinterpret_cast<const __half2*>(&r1);
#pragma unroll
        for (int j = 0; j < 4; j++) {
            float2 v0 = __half22float2(h0[j]);
            float2 v1 = __half22float2(h1[j]);
            acc[j * 2 + 0] += v0.x * w0 + v1.x * w1;
            acc[j * 2 + 1] += v0.y * w0 + v1.y * w1;
        }
    }
    if (p < p1) {
        int2 c0 = g_csr[p];
        float w0 = __int_as_float(c0.y);
        uint4 r0 = m4[(size_t)c0.x * 8 + ft];
        const __half2* h0 = reinterpret_cast<const __half2*>(&r0);
#pragma unroll
        for (int j = 0; j < 4; j++) {
            float2 v0 = __half22float2(h0[j]);
            acc[j * 2 + 0] += v0.x * w0;
            acc[j * 2 + 1] += v0.y * w0;
        }
    }

    float di = g_dinv[gid];
    const float* bp = b + ft * 8;
    __align__(16) __half2 o[4];
#pragma unroll
    for (int j = 0; j < 4; j++) {
        float r0 = fmaxf(acc[j * 2 + 0] * di + bp[j * 2 + 0], 0.f);
        float r1 = fmaxf(acc[j * 2 + 1] * di + bp[j * 2 + 1], 0.f);
        o[j] = __floats2half2_rn(r0, r1);
    }
    *reinterpret_cast<uint4*>(h + (size_t)gid * 64 + ft * 8) = *reinterpret_cast<uint4*>(o);
}

// ---------------- agg layer1 + fused pooling into g_pool ----------------
__global__ void node_agg1_pool_kernel(const __half* __restrict__ m, const float* __restrict__ b,
                                      const int* __restrict__ ngi, int n) {
    int gid = (blockIdx.x * blockDim.x + threadIdx.x) >> 2;
    int ft = threadIdx.x & 3;
    if (gid >= n) return;
    const uint4* m4 = reinterpret_cast<const uint4*>(m);   // row stride 4 uint4

    float acc[8];
    {
        uint4 raw = m4[(size_t)gid * 4 + ft];
        const __half2* hp = reinterpret_cast<const __half2*>(&raw);
#pragma unroll
        for (int j = 0; j < 4; j++) {
            float2 v = __half22float2(hp[j]);
            acc[j * 2 + 0] = v.x;
            acc[j * 2 + 1] = v.y;
        }
    }

    int p = g_rs[gid], p1 = g_rs[gid + 1];
    for (; p + 1 < p1; p += 2) {
        int2 c0 = g_csr[p], c1 = g_csr[p + 1];
        float w0 = __int_as_float(c0.y), w1 = __int_as_float(c1.y);
        uint4 r0 = m4[(size_t)c0.x * 4 + ft];
        uint4 r1 = m4[(size_t)c1.x * 4 + ft];
        const __half2* h0 = reinterpret_cast<const __half2*>(&r0);
        const __half2* h1 = reinterpret_cast<const __half2*>(&r1);
#pragma unroll
        for (int j = 0; j < 4; j++) {
            float2 v0 = __half22float2(h0[j]);
            float2 v1 = __half22float2(h1[j]);
            acc[j * 2 + 0] += v0.x * w0 + v1.x * w1;
            acc[j * 2 + 1] += v0.y * w0 + v1.y * w1;
        }
    }
    if (p < p1) {
        int2 c0 = g_csr[p];
        float w0 = __int_as_float(c0.y);
        uint4 r0 = m4[(size_t)c0.x * 4 + ft];
        const __half2* h0 = reinterpret_cast<const __half2*>(&r0);
#pragma unroll
        for (int j = 0; j < 4; j++) {
            float2 v0 = __half22float2(h0[j]);
            acc[j * 2 + 0] += v0.x * w0;
            acc[j * 2 + 1] += v0.y * w0;
        }
    }

    float di = g_dinv[gid];
    const float* bp = b + ft * 8;
    float v0 = fmaxf(acc[0] * di + bp[0], 0.f);
    float v1 = fmaxf(acc[1] * di + bp[1], 0.f);
    float v2 = fmaxf(acc[2] * di + bp[2], 0.f);
    float v3 = fmaxf(acc[3] * di + bp[3], 0.f);
    float v4 = fmaxf(acc[4] * di + bp[4], 0.f);
    float v5 = fmaxf(acc[5] * di + bp[5], 0.f);
    float v6 = fmaxf(acc[6] * di + bp[6], 0.f);
    float v7 = fmaxf(acc[7] * di + bp[7], 0.f);

    int graph = ngi[gid];
    float* pp = &g_pool[graph * 32 + ft * 8];
    asm volatile("red.global.add.v4.f32 [%0], {%1, %2, %3, %4};"
                 :: "l"(pp), "f"(v0), "f"(v1), "f"(v2), "f"(v3) : "memory");
    asm volatile("red.global.add.v4.f32 [%0], {%1, %2, %3, %4};"
                 :: "l"(pp + 4), "f"(v4), "f"(v5), "f"(v6), "f"(v7) : "memory");
}

// ---------------- MLP head + scratch cleanup for the next replay ----------------
__global__ void mlp_kernel(const float* __restrict__ Wm1, const float* __restrict__ bm1,
                           const float* __restrict__ Wm2, const float* __restrict__ bm2,
                           float* __restrict__ out) {
    __shared__ float gs[32];
    __shared__ float g2s[128];
    int b = blockIdx.x, t = threadIdx.x;

    int idx = b * 128 + t;
    if (idx < N_NODES) g_cnt[idx] = 0;

    if (t < 32) {
        gs[t] = g_pool[b * 32 + t];
        g_pool[b * 32 + t] = 0.f;      // same thread read-then-zero: safe
    }
    __syncthreads();
    float a1 = bm1[t];
#pragma unroll
    for (int k = 0; k < 32; k++) a1 += gs[k] * Wm1[k * 128 + t];
    g2s[t] = fmaxf(a1, 0.f);
    __syncthreads();
    if (t < 2) {
        float a = bm2[t];
#pragma unroll
        for (int k = 0; k < 128; k++) a += g2s[k] * Wm2[k * 2 + t];
        out[b * 2 + t] = a;
    }
}

// ---------------- host ----------------
extern "C" void kernel_launch(void* const* d_in, const int* in_sizes, int n_in,
                              void* d_out, int out_size) {
    const float* x   = (const float*)d_in[0];
    const int*   ei  = (const int*)d_in[1];
    const float* ew  = (const float*)d_in[2];
    const int*   ngi = (const int*)d_in[3];
    const float* W0  = (const float*)d_in[4];
    const float* b0  = (const float*)d_in[5];
    const float* W1  = (const float*)d_in[6];
    const float* b1  = (const float*)d_in[7];
    const float* Wm1 = (const float*)d_in[8];
    const float* bm1 = (const float*)d_in[9];
    const float* Wm2 = (const float*)d_in[10];
    const float* bm2 = (const float*)d_in[11];
    float* out = (float*)d_out;

    const int* srcp = ei;
    const int* dstp = ei + N_EDGES;

    static cudaStream_t s2 = nullptr;
    static cudaEvent_t  e_fork = nullptr, e_scan = nullptr, e_sc1 = nullptr, e_join = nullptr;
    if (s2 == nullptr) {
        cudaStreamCreateWithFlags(&s2, cudaStreamNonBlocking);
        cudaEventCreateWithFlags(&e_fork, cudaEventDisableTiming);
        cudaEventCreateWithFlags(&e_scan, cudaEventDisableTiming);
        cudaEventCreateWithFlags(&e_sc1,  cudaEventDisableTiming);
        cudaEventCreateWithFlags(&e_join, cudaEventDisableTiming);
    }

    void *p_m, *p_h, *p_m2;
    cudaGetSymbolAddress(&p_m,  g_m);
    cudaGetSymbolAddress(&p_h,  g_h);
    cudaGetSymbolAddress(&p_m2, g_m2);

    const int EH = N_EDGES / 2;            // 800000, divisible by 4

    // ---- fork ----
    cudaEventRecord(e_fork, 0);
    cudaStreamWaitEvent(s2, e_fork, 0);

    // s2: count/rank + scan
    edge_prep_kernel<<<(N_EDGES / 4 + 255) / 256, 256, 0, s2>>>(dstp, N_EDGES);
    scan1_kernel<<<N_SBLK, SCAN_B, 0, s2>>>(N_NODES);
    scan23_kernel<<<N_SBLK, SCAN_B, 0, s2>>>(N_NODES);
    cudaEventRecord(e_scan, s2);

    // main: layer-0 GEMM concurrent with the scan chain, then scatter half B
    gemm_tf32_kernel<float, 128, 64, 128, 64, false>
        <<<(N_NODES + 127) / 128, 256>>>(x, W0, (__half*)p_m, N_NODES);
    cudaStreamWaitEvent(0, e_scan, 0);
    scatter_kernel<<<(EH / 4 + 255) / 256, 256>>>(srcp, dstp, ew, EH, N_EDGES);
    cudaEventRecord(e_sc1, 0);

    // s2: scatter half A, then deg+dinv after both halves
    scatter_kernel<<<(EH / 4 + 255) / 256, 256, 0, s2>>>(srcp, dstp, ew, 0, EH);
    cudaStreamWaitEvent(s2, e_sc1, 0);
    degdinv_kernel<<<(N_NODES + 255) / 256, 256, 0, s2>>>(N_NODES);
    cudaEventRecord(e_join, s2);

    // ---- join, then the serial tail on main ----
    cudaStreamWaitEvent(0, e_join, 0);

    scale_m_kernel<<<(N_NODES * 8 + 255) / 256, 256>>>((__half*)p_m);
    node_agg0_kernel<<<(N_NODES * 8 + 255) / 256, 256>>>((const __half*)p_m, b0, (__half*)p_h, N_NODES);
    gemm_tf32_kernel<__half, 64, 32, 128, 64, true>
        <<<(N_NODES + 127) / 128, 256>>>((const __half*)p_h, W1, (__half*)p_m2, N_NODES);
    node_agg1_pool_kernel<<<(N_NODES * 4 + 255) / 256, 256>>>((const __half*)p_m2, b1, ngi, N_NODES);

    mlp_kernel<<<N_GRAPHS, 128>>>(Wm1, bm1, Wm2, bm2, out);
}